// round 10
// baseline (speedup 1.0000x reference)
#include <cuda_runtime.h>

// Problem constants
#define Tn   2048
#define Dn   1024
#define Hn   16
#define HDn  64
#define Bn   2
#define ROWS (Bn * Tn)   // 4096
#define ZHD  (Bn * Hn)   // 32

// ---------------- scratch (static device globals; no allocations) ----------
__device__ float g_h1 [ROWS * Dn];
__device__ float g_qkv[ZHD * Tn * 192];          // fused q|k|v per (b,h), tf32-rounded
__device__ float g_vt [ZHD * HDn * Tn];          // V^T per (b,h), tf32-rounded
__device__ float g_att[ROWS * Dn];
__device__ float g_x2 [ROWS * Dn];
__device__ float g_h2 [ROWS * Dn];
__device__ float g_mid[ROWS * 4 * Dn];
__device__ float g_wqkvT[Hn * 256 * Dn];         // [H][256][D], rows 192..255 stay zero
__device__ float g_woT [Dn * Dn];
__device__ float g_w1T [4 * Dn * Dn];            // [4D][D]
__device__ float g_w2T [4 * Dn * Dn];            // [D][4D]

// ---------------------------------------------------------------------------
__device__ __forceinline__ float rna(float x) {
    unsigned u;
    asm("cvt.rna.tf32.f32 %0, %1;" : "=r"(u) : "f"(x));
    return __uint_as_float(u);
}
__device__ __forceinline__ unsigned smem_u32(const void* p) {
    return (unsigned)__cvta_generic_to_shared(p);
}
__device__ __forceinline__ void cp16(unsigned dst, const void* src) {
    asm volatile("cp.async.cg.shared.global [%0],[%1],16;\n" :: "r"(dst), "l"(src));
}
#define CP_COMMIT()  asm volatile("cp.async.commit_group;" ::: "memory")
#define CP_WAIT(n)   asm volatile("cp.async.wait_group %0;" :: "n"(n) : "memory")

#define MMA_TF32(d, a, b) \
    asm volatile("mma.sync.aligned.m16n8k8.row.col.f32.tf32.tf32.f32 " \
                 "{%0,%1,%2,%3},{%4,%5,%6,%7},{%8,%9},{%0,%1,%2,%3};\n" \
                 : "+f"((d)[0]), "+f"((d)[1]), "+f"((d)[2]), "+f"((d)[3]) \
                 : "r"((a)[0]), "r"((a)[1]), "r"((a)[2]), "r"((a)[3]), \
                   "r"((b)[0]), "r"((b)[1]))

// ---------------------------------------------------------------------------
// transpose + tf32-round: in [z][R][C] fp32 (row stride ldin) -> out [z][C][R]
// ---------------------------------------------------------------------------
__global__ void transpose_rna(const float* __restrict__ in,
                              float* __restrict__ outp,
                              int ldin, long long sIn, int ldout, long long sOut)
{
    __shared__ float t[32][33];
    int z = blockIdx.z;
    in   += (long long)z * sIn;
    outp += (long long)z * sOut;
    int c0 = blockIdx.x * 32, r0 = blockIdx.y * 32;
    int tx = threadIdx.x, ty = threadIdx.y;
#pragma unroll
    for (int i = 0; i < 32; i += 8)
        t[ty + i][tx] = in[(long long)(r0 + ty + i) * ldin + c0 + tx];
    __syncthreads();
#pragma unroll
    for (int i = 0; i < 32; i += 8)
        outp[(long long)(c0 + ty + i) * ldout + r0 + tx] = rna(t[tx][ty + i]);
}

// ---------------------------------------------------------------------------
// gemm_tf32: single-pass TF32 GEMM. C = A @ B^T (+epi).
//   A fp32 [M,K] (tf32-rounded by producer); B fp32 [N,K] (rounded); fp32 acc.
//   EPI: 0 -> rounded fp32 C, guard cc<N; 1 -> bias+relu, rounded fp32 C;
//        2 -> bias+residual, exact fp32 C.
// BM=128, BN=128, BK=32, 256 thr (warps 2m x 4n, warp tile 64x32),
// 3-stage cp.async pipeline, ONE __syncthreads per K-iteration:
//   order = wait(1) -> sync -> issue load kt+2 -> compute kt.
// All warps past sync_kt have finished compute kt-1, so the load into
// (kt+2)%3 == (kt-1)%3 is race-free without a trailing barrier.
// Dynamic smem: 3 * 8192 floats = 96 KB.
// ---------------------------------------------------------------------------
template <int EPI>
__launch_bounds__(256, 2)
__global__ void gemm_tf32(const float* __restrict__ A,
                          const float* __restrict__ B,
                          float* __restrict__ C,
                          const float* __restrict__ bias,
                          const float* __restrict__ res,
                          int N, int K, int lda, int ldb, int ldc,
                          long long sA1, int dA, long long sA2, int mA,
                          long long sB1, int dB, long long sB2, int mB,
                          long long sC1, int dC, long long sC2, int mC)
{
    extern __shared__ float sm[];      // stage s: A at s*8192, B at s*8192+4096

    const int m0 = blockIdx.y * 128;
    const int n0 = blockIdx.x * 128;

    const int z = blockIdx.z;
    A += (long long)(z / dA) * sA1 + (long long)(z % mA) * sA2;
    B += (long long)(z / dB) * sB1 + (long long)(z % mB) * sB2;
    const long long coff = (long long)(z / dC) * sC1 + (long long)(z % mC) * sC2;
    C += coff;
    if (EPI == 2) res += coff;

    const int tid  = threadIdx.x;
    const int lane = tid & 31;
    const int w    = tid >> 5;
    const int wm   = (w & 1) * 64;
    const int wn   = (w >> 1) * 32;
    const int q    = lane >> 2;
    const int kb   = lane & 3;
    const int nk   = K / 32;

    // loader constants: thread handles rows (tid>>3)+32i, float4 group tid&7
    const int lrow = tid >> 3;
    const int lg   = tid & 7;
    const unsigned lsw = ((unsigned)(lg * 4)) ^ ((unsigned)((lrow & 7) * 4));

    float acc[4][4][4];
#pragma unroll
    for (int mt = 0; mt < 4; mt++)
#pragma unroll
        for (int nt = 0; nt < 4; nt++)
#pragma unroll
            for (int j = 0; j < 4; j++) acc[mt][nt][j] = 0.f;

    auto load_stage = [&](int st, int kt) {
        float* sb = sm + st * 8192;
        const int k0 = kt * 32;
#pragma unroll
        for (int i = 0; i < 4; i++) {
            int row = lrow + 32 * i;
            unsigned off = row * 32 + lsw;
            cp16(smem_u32(sb + off),        A + (long long)(m0 + row) * lda + k0 + lg * 4);
            cp16(smem_u32(sb + 4096 + off), B + (long long)(n0 + row) * ldb + k0 + lg * 4);
        }
        CP_COMMIT();
    };

    load_stage(0, 0);
    load_stage(1, 1);               // nk >= 2 for all shapes here (K >= 1024)

    for (int kt = 0; kt < nk; kt++) {
        if (kt + 1 < nk) { CP_WAIT(1); } else { CP_WAIT(0); }
        __syncthreads();
        if (kt + 2 < nk) load_stage((kt + 2) % 3, kt + 2);

        const unsigned* su = (const unsigned*)(sm + (kt % 3) * 8192);
        const unsigned qx = (unsigned)(q << 2);
#pragma unroll
        for (int s4 = 0; s4 < 4; s4++) {
            const int k8 = s4 * 8;
            const unsigned g0 = ((unsigned)k8 ^ qx) + kb;
            const unsigned g1 = ((unsigned)(k8 + 4) ^ qx) + kb;
            unsigned a[4][4], b[4][2];
#pragma unroll
            for (int mt = 0; mt < 4; mt++) {
                const int r = wm + mt * 16 + q;
                a[mt][0] = su[r * 32 + g0];
                a[mt][1] = su[(r + 8) * 32 + g0];
                a[mt][2] = su[r * 32 + g1];
                a[mt][3] = su[(r + 8) * 32 + g1];
            }
#pragma unroll
            for (int nt = 0; nt < 4; nt++) {
                const int rn = wn + nt * 8 + q;
                b[nt][0] = su[4096 + rn * 32 + g0];
                b[nt][1] = su[4096 + rn * 32 + g1];
            }
#pragma unroll
            for (int mt = 0; mt < 4; mt++)
#pragma unroll
                for (int nt = 0; nt < 4; nt++)
                    MMA_TF32(acc[mt][nt], a[mt], b[nt]);
        }
    }

    // ---- epilogue
#pragma unroll
    for (int mt = 0; mt < 4; mt++)
#pragma unroll
        for (int nt = 0; nt < 4; nt++) {
            const float* a4 = acc[mt][nt];
            const long long r0 = m0 + wm + mt * 16 + q;
            const long long r1 = r0 + 8;
            const int cc = n0 + wn + nt * 8 + kb * 2;
            if (EPI == 0) {
                if (cc < N) {
                    *reinterpret_cast<float2*>(&C[r0 * ldc + cc]) =
                        make_float2(rna(a4[0]), rna(a4[1]));
                    *reinterpret_cast<float2*>(&C[r1 * ldc + cc]) =
                        make_float2(rna(a4[2]), rna(a4[3]));
                }
            } else if (EPI == 1) {
                float2 bv = *reinterpret_cast<const float2*>(&bias[cc]);
                *reinterpret_cast<float2*>(&C[r0 * ldc + cc]) =
                    make_float2(rna(fmaxf(a4[0] + bv.x, 0.f)),
                                rna(fmaxf(a4[1] + bv.y, 0.f)));
                *reinterpret_cast<float2*>(&C[r1 * ldc + cc]) =
                    make_float2(rna(fmaxf(a4[2] + bv.x, 0.f)),
                                rna(fmaxf(a4[3] + bv.y, 0.f)));
            } else {
                float2 bv = *reinterpret_cast<const float2*>(&bias[cc]);
                float2 q0 = *reinterpret_cast<const float2*>(&res[r0 * ldc + cc]);
                float2 q1 = *reinterpret_cast<const float2*>(&res[r1 * ldc + cc]);
                *reinterpret_cast<float2*>(&C[r0 * ldc + cc]) =
                    make_float2(a4[0] + bv.x + q0.x, a4[1] + bv.y + q0.y);
                *reinterpret_cast<float2*>(&C[r1 * ldc + cc]) =
                    make_float2(a4[2] + bv.x + q1.x, a4[3] + bv.y + q1.y);
            }
        }
}

// ---------------------------------------------------------------------------
// Flash attention, single-pass TF32 with 2-stage K/V pipeline.
// 128 query rows per block, 64-key tiles. ONE __syncthreads per tile:
//   order = wait(0) -> sync -> issue load it+1 -> compute it.
// (All warps past sync_it finished compute it-1, so the load into
//  (it+1)&1 == (it-1)&1 is race-free.)
// Q staged in dynamic smem before the pipeline starts.
// grid = (Tn/128, ZHD), block = 256. Dynamic smem: 2 * 8192 floats = 64 KB.
// ---------------------------------------------------------------------------
__launch_bounds__(256)
__global__ void flash_tf32(const float* __restrict__ qkv,
                           const float* __restrict__ vt,
                           float* __restrict__ att)
{
    extern __shared__ float s_u[];   // 16384 floats: Q staging, then 2 KV stages

    const int z  = blockIdx.y;
    const int m0 = blockIdx.x * 128;
    const int tid = threadIdx.x, lane = tid & 31, w = tid >> 5;
    const int q  = lane >> 2;
    const int kb = lane & 3;
    const unsigned qx = (unsigned)(q << 2);

    // ---- stage Q (128x68), extract tf32 A-fragments (scale 2^-5 folded)
    unsigned qf[8][4];
    {
        const float* Qg = qkv + (long long)z * Tn * 192 + (long long)m0 * 192;
#pragma unroll
        for (int i = 0; i < 8; i++) {
            int idx = tid + 256 * i;
            int r = idx >> 4, c4 = idx & 15;
            float4 v = *reinterpret_cast<const float4*>(Qg + (long long)r * 192 + c4 * 4);
            *reinterpret_cast<float4*>(s_u + r * 68 + c4 * 4) = v;
        }
        __syncthreads();
        const int ra = w * 16 + q;
        const float sc = 0.03125f;      // exact power of 2, keeps tf32-exactness
#pragma unroll
        for (int c = 0; c < 8; c++) {
            qf[c][0] = __float_as_uint(s_u[ra * 68 + c * 8 + kb] * sc);
            qf[c][1] = __float_as_uint(s_u[(ra + 8) * 68 + c * 8 + kb] * sc);
            qf[c][2] = __float_as_uint(s_u[ra * 68 + c * 8 + kb + 4] * sc);
            qf[c][3] = __float_as_uint(s_u[(ra + 8) * 68 + c * 8 + kb + 4] * sc);
        }
        __syncthreads();                // Q staging area free; pipeline may reuse it
    }

    float m0s = -1e30f, m1s = -1e30f;
    float l0 = 0.f, l1 = 0.f;
    float acc_o[8][4];
#pragma unroll
    for (int nt = 0; nt < 8; nt++)
#pragma unroll
        for (int j = 0; j < 4; j++) acc_o[nt][j] = 0.f;

    const int nkb = blockIdx.x * 2 + 2;
    const float* Kg = qkv + (long long)z * Tn * 192 + 64;
    const float* Vg = vt + (long long)z * HDn * Tn;
    const int rga = m0 + w * 16 + q;
    const int rgb = rga + 8;

    // loader constants: rows (tid>>4)+16i, float4 group tid&15
    const int lrow = tid >> 4;
    const int lg   = tid & 15;
    const unsigned lsw = ((unsigned)(lg * 4)) ^ ((unsigned)((lrow & 7) * 4));

    // K tile at sb[0..4095], V tile at sb[4096..8191]
    auto load_kv = [&](int st, int it) {
        float* sb = s_u + st * 8192;
#pragma unroll
        for (int i = 0; i < 4; i++) {
            int row = lrow + 16 * i;
            unsigned off = row * 64 + lsw;
            cp16(smem_u32(sb + off),
                 Kg + (long long)(it * 64 + row) * 192 + lg * 4);
            cp16(smem_u32(sb + 4096 + off),
                 Vg + (long long)row * Tn + it * 64 + lg * 4);
        }
        CP_COMMIT();
    };

    load_kv(0, 0);

    for (int it = 0; it < nkb; it++) {
        CP_WAIT(0);                         // only one group in flight at a time
        __syncthreads();
        if (it + 1 < nkb) load_kv((it + 1) & 1, it + 1);   // overlaps compute below

        const unsigned* su = (const unsigned*)(s_u + (it & 1) * 8192);

        // ---- S = Q K^T (tf32)
        float s[8][4];
#pragma unroll
        for (int nt = 0; nt < 8; nt++)
#pragma unroll
            for (int j = 0; j < 4; j++) s[nt][j] = 0.f;

#pragma unroll
        for (int c = 0; c < 8; c++) {
            const int c8 = c * 8;
            const unsigned g0 = ((unsigned)c8 ^ qx) + kb;
            const unsigned g1 = ((unsigned)(c8 + 4) ^ qx) + kb;
#pragma unroll
            for (int nt = 0; nt < 8; nt++) {
                const int ro = (nt * 8 + q) * 64;
                unsigned bb[2] = { su[ro + g0], su[ro + g1] };
                MMA_TF32(s[nt], qf[c], bb);
            }
        }

        // ---- causal mask
        const int cb = kb * 2;
        if (it * 64 + 63 > rga) {
#pragma unroll
            for (int nt = 0; nt < 8; nt++) {
                int cg = it * 64 + nt * 8 + cb;
                if (cg > rga)     s[nt][0] = -1e30f;
                if (cg + 1 > rga) s[nt][1] = -1e30f;
                if (cg > rgb)     s[nt][2] = -1e30f;
                if (cg + 1 > rgb) s[nt][3] = -1e30f;
            }
        }

        // ---- online softmax
        float ml0 = -1e30f, ml1 = -1e30f;
#pragma unroll
        for (int nt = 0; nt < 8; nt++) {
            ml0 = fmaxf(ml0, fmaxf(s[nt][0], s[nt][1]));
            ml1 = fmaxf(ml1, fmaxf(s[nt][2], s[nt][3]));
        }
        ml0 = fmaxf(ml0, __shfl_xor_sync(0xffffffffu, ml0, 1));
        ml0 = fmaxf(ml0, __shfl_xor_sync(0xffffffffu, ml0, 2));
        ml1 = fmaxf(ml1, __shfl_xor_sync(0xffffffffu, ml1, 1));
        ml1 = fmaxf(ml1, __shfl_xor_sync(0xffffffffu, ml1, 2));
        float mn0 = fmaxf(m0s, ml0), mn1 = fmaxf(m1s, ml1);
        float al0 = __expf(m0s - mn0), al1 = __expf(m1s - mn1);
        m0s = mn0; m1s = mn1;

        float rs0 = 0.f, rs1 = 0.f;
#pragma unroll
        for (int nt = 0; nt < 8; nt++) {
            s[nt][0] = __expf(s[nt][0] - mn0);
            s[nt][1] = __expf(s[nt][1] - mn0);
            s[nt][2] = __expf(s[nt][2] - mn1);
            s[nt][3] = __expf(s[nt][3] - mn1);
            rs0 += s[nt][0] + s[nt][1];
            rs1 += s[nt][2] + s[nt][3];
        }
        rs0 += __shfl_xor_sync(0xffffffffu, rs0, 1);
        rs0 += __shfl_xor_sync(0xffffffffu, rs0, 2);
        rs1 += __shfl_xor_sync(0xffffffffu, rs1, 1);
        rs1 += __shfl_xor_sync(0xffffffffu, rs1, 2);
        l0 = l0 * al0 + rs0;
        l1 = l1 * al1 + rs1;
#pragma unroll
        for (int nt = 0; nt < 8; nt++) {
            acc_o[nt][0] *= al0; acc_o[nt][1] *= al0;
            acc_o[nt][2] *= al1; acc_o[nt][3] *= al1;
        }

        // ---- O += P V: shuffle-transpose P C-frag -> A-frag per key chunk
        const int src0 = (lane & ~3) | (kb >> 1);
        const int src1 = src0 + 2;
        const bool od = (kb & 1);
#pragma unroll
        for (int kc = 0; kc < 8; kc++) {
            float x0 = __shfl_sync(0xffffffffu, s[kc][0], src0);
            float x1 = __shfl_sync(0xffffffffu, s[kc][1], src0);
            float x2 = __shfl_sync(0xffffffffu, s[kc][2], src0);
            float x3 = __shfl_sync(0xffffffffu, s[kc][3], src0);
            float y0 = __shfl_sync(0xffffffffu, s[kc][0], src1);
            float y1 = __shfl_sync(0xffffffffu, s[kc][1], src1);
            float y2 = __shfl_sync(0xffffffffu, s[kc][2], src1);
            float y3 = __shfl_sync(0xffffffffu, s[kc][3], src1);
            unsigned pa[4];
            pa[0] = __float_as_uint(rna(od ? x1 : x0));
            pa[1] = __float_as_uint(rna(od ? x3 : x2));
            pa[2] = __float_as_uint(rna(od ? y1 : y0));
            pa[3] = __float_as_uint(rna(od ? y3 : y2));
            const int k8 = kc * 8;
            const unsigned g0 = ((unsigned)k8 ^ qx) + kb;
            const unsigned g1 = ((unsigned)(k8 + 4) ^ qx) + kb;
#pragma unroll
            for (int nt = 0; nt < 8; nt++) {
                const int ro = 4096 + (nt * 8 + q) * 64;
                unsigned bb[2] = { su[ro + g0], su[ro + g1] };
                MMA_TF32(acc_o[nt], pa, bb);
            }
        }
        // no trailing sync: next iteration's load targets the other buffer,
        // and its top-of-loop sync orders buffer reuse.
    }

    // ---- epilogue: normalize, round, write concat layout [b][t][h*64+e]
    const float i0 = 1.f / l0, i1 = 1.f / l1;
    float* op = att + (long long)(z >> 4) * Tn * Dn + (z & 15) * HDn;
    const int cb = kb * 2;
#pragma unroll
    for (int nt = 0; nt < 8; nt++) {
        *reinterpret_cast<float2*>(op + (long long)rga * Dn + nt * 8 + cb) =
            make_float2(rna(acc_o[nt][0] * i0), rna(acc_o[nt][1] * i0));
        *reinterpret_cast<float2*>(op + (long long)rgb * Dn + nt * 8 + cb) =
            make_float2(rna(acc_o[nt][2] * i1), rna(acc_o[nt][3] * i1));
    }
}

// ---------------------------------------------------------------------------
// LayerNorm over last dim (1024), output tf32-rounded fp32.
// ---------------------------------------------------------------------------
__launch_bounds__(256)
__global__ void ln_kernel(const float* __restrict__ x,
                          const float* __restrict__ g,
                          const float* __restrict__ be,
                          float* __restrict__ outp)
{
    long long row = blockIdx.x;
    const float* xr = x + row * Dn;
    int tid = threadIdx.x;

    float v[4];
    float s = 0.f;
#pragma unroll
    for (int i = 0; i < 4; i++) { v[i] = xr[tid + 256 * i]; s += v[i]; }

    __shared__ float red[8];
    __shared__ float sh_mu, sh_rstd;

#pragma unroll
    for (int o = 16; o > 0; o >>= 1) s += __shfl_xor_sync(0xffffffffu, s, o);
    if ((tid & 31) == 0) red[tid >> 5] = s;
    __syncthreads();
    if (tid == 0) {
        float t = 0.f;
        for (int i = 0; i < 8; i++) t += red[i];
        sh_mu = t * (1.0f / Dn);
    }
    __syncthreads();
    float mu = sh_mu;

    float ss = 0.f;
#pragma unroll
    for (int i = 0; i < 4; i++) { float d = v[i] - mu; ss += d * d; }
#pragma unroll
    for (int o = 16; o > 0; o >>= 1) ss += __shfl_xor_sync(0xffffffffu, ss, o);
    if ((tid & 31) == 0) red[tid >> 5] = ss;
    __syncthreads();
    if (tid == 0) {
        float t = 0.f;
        for (int i = 0; i < 8; i++) t += red[i];
        sh_rstd = rsqrtf(t * (1.0f / Dn) + 1e-5f);
    }
    __syncthreads();
    float rstd = sh_rstd;

#pragma unroll
    for (int i = 0; i < 4; i++) {
        int c = tid + 256 * i;
        outp[row * Dn + c] = rna((v[i] - mu) * rstd * g[c] + be[c]);
    }
}

// ---------------------------------------------------------------------------
extern "C" void kernel_launch(void* const* d_in, const int* in_sizes, int n_in,
                              void* d_out, int out_size)
{
    const float* x   = (const float*)d_in[0];
    const float* Wq  = (const float*)d_in[1];
    const float* Wk  = (const float*)d_in[2];
    const float* Wv  = (const float*)d_in[3];
    const float* Wo  = (const float*)d_in[4];
    const float* bo  = (const float*)d_in[5];
    const float* W1  = (const float*)d_in[6];
    const float* b1  = (const float*)d_in[7];
    const float* W2  = (const float*)d_in[8];
    const float* b2  = (const float*)d_in[9];
    const float* g1  = (const float*)d_in[10];
    const float* be1 = (const float*)d_in[11];
    const float* g2  = (const float*)d_in[12];
    const float* be2 = (const float*)d_in[13];
    float* out = (float*)d_out;

    float *h1, *qkv, *vt, *att, *x2, *h2, *mid;
    float *wqkvT, *woT, *w1T, *w2T;
    cudaGetSymbolAddress((void**)&h1,   g_h1);
    cudaGetSymbolAddress((void**)&qkv,  g_qkv);
    cudaGetSymbolAddress((void**)&vt,   g_vt);
    cudaGetSymbolAddress((void**)&att,  g_att);
    cudaGetSymbolAddress((void**)&x2,   g_x2);
    cudaGetSymbolAddress((void**)&h2,   g_h2);
    cudaGetSymbolAddress((void**)&mid,  g_mid);
    cudaGetSymbolAddress((void**)&wqkvT, g_wqkvT);
    cudaGetSymbolAddress((void**)&woT,  g_woT);
    cudaGetSymbolAddress((void**)&w1T,  g_w1T);
    cudaGetSymbolAddress((void**)&w2T,  g_w2T);

    const int GSMEM = 3 * 8192 * 4;    // 96 KB (3-stage)
    cudaFuncSetAttribute(gemm_tf32<0>, cudaFuncAttributeMaxDynamicSharedMemorySize, GSMEM);
    cudaFuncSetAttribute(gemm_tf32<1>, cudaFuncAttributeMaxDynamicSharedMemorySize, GSMEM);
    cudaFuncSetAttribute(gemm_tf32<2>, cudaFuncAttributeMaxDynamicSharedMemorySize, GSMEM);
    const int FSMEM = 2 * 8192 * 4;    // 64 KB (2-stage KV + Q staging overlay)
    cudaFuncSetAttribute(flash_tf32, cudaFuncAttributeMaxDynamicSharedMemorySize, FSMEM);

    dim3 blk(256);
    dim3 tblk(32, 8);

    // ---- weight transposes (+ tf32 rounding); wqkvT rows 192..255 remain zero
    transpose_rna<<<dim3(HDn / 32, Dn / 32, Hn), tblk>>>(
        Wq, wqkvT + 0 * HDn * Dn, HDn, (long long)Dn * HDn, Dn, (long long)256 * Dn);
    transpose_rna<<<dim3(HDn / 32, Dn / 32, Hn), tblk>>>(
        Wk, wqkvT + 1 * HDn * Dn, HDn, (long long)Dn * HDn, Dn, (long long)256 * Dn);
    transpose_rna<<<dim3(HDn / 32, Dn / 32, Hn), tblk>>>(
        Wv, wqkvT + 2 * HDn * Dn, HDn, (long long)Dn * HDn, Dn, (long long)256 * Dn);
    transpose_rna<<<dim3(Dn / 32, Dn / 32, 1), tblk>>>(
        Wo, woT, Dn, 0LL, Dn, 0LL);
    transpose_rna<<<dim3(4 * Dn / 32, Dn / 32, 1), tblk>>>(
        W1, w1T, 4 * Dn, 0LL, Dn, 0LL);
    transpose_rna<<<dim3(Dn / 32, 4 * Dn / 32, 1), tblk>>>(
        W2, w2T, Dn, 0LL, 4 * Dn, 0LL);

    // ---- LN1: x -> h1 (rounded)
    ln_kernel<<<ROWS, blk>>>(x, g1, be1, h1);

    // ---- fused QKV: qkv[z][T][192] = h1(b) @ wqkvT(h)^T ; z = b*H + h
    gemm_tf32<0><<<dim3(2, Tn / 128, ZHD), blk, GSMEM>>>(
        h1, wqkvT, qkv, nullptr, nullptr,
        192, Dn, Dn, Dn, 192,
        (long long)Tn * Dn, Hn, 0LL, 1,          // A: per batch b = z/H
        0LL, 1, (long long)256 * Dn, Hn,         // B: per head h = z%H (padded)
        (long long)Tn * 192, 1, 0LL, 1);         // C: per z

    // ---- V transpose (rounded): qkv[:, :, 128:192] -> vt [z][HD][T]
    transpose_rna<<<dim3(HDn / 32, Tn / 32, ZHD), tblk>>>(
        qkv + 128, vt, 192, (long long)Tn * 192, Tn, (long long)HDn * Tn);

    // ---- flash attention (tf32) -> att (rounded, concat layout)
    flash_tf32<<<dim3(Tn / 128, ZHD), blk, FSMEM>>>(qkv, vt, att);

    // ---- O projection + bias + residual: x2 = x + att @ Wo + bo
    gemm_tf32<2><<<dim3(Dn / 128, ROWS / 128, 1), blk, GSMEM>>>(
        att, woT, x2, bo, x,
        Dn, Dn, Dn, Dn, Dn,
        0LL, 1, 0LL, 1, 0LL, 1, 0LL, 1, 0LL, 1, 0LL, 1);

    // ---- LN2: x2 -> h2 (rounded)
    ln_kernel<<<ROWS, blk>>>(x2, g2, be2, h2);

    // ---- FFN1: mid = relu(h2 @ W1 + b1) (rounded)
    gemm_tf32<1><<<dim3(4 * Dn / 128, ROWS / 128, 1), blk, GSMEM>>>(
        h2, w1T, mid, b1, nullptr,
        4 * Dn, Dn, Dn, Dn, 4 * Dn,
        0LL, 1, 0LL, 1, 0LL, 1, 0LL, 1, 0LL, 1, 0LL, 1);

    // ---- FFN2: out = x2 + mid @ W2 + b2
    gemm_tf32<2><<<dim3(Dn / 128, ROWS / 128, 1), blk, GSMEM>>>(
        mid, w2T, out, b2, x2,
        Dn, 4 * Dn, 4 * Dn, 4 * Dn, Dn,
        0LL, 1, 0LL, 1, 0LL, 1, 0LL, 1, 0LL, 1, 0LL, 1);
}

// round 11
// speedup vs baseline: 1.0879x; 1.0879x over previous
#include <cuda_runtime.h>

// Problem constants
#define Tn   2048
#define Dn   1024
#define Hn   16
#define HDn  64
#define Bn   2
#define ROWS (Bn * Tn)   // 4096
#define ZHD  (Bn * Hn)   // 32
#define NQKV 3072        // q|k|v fused output width (16 heads x 64 each)

// ---------------- scratch (static device globals; no allocations) ----------
__device__ float g_h1 [ROWS * Dn];
__device__ float g_qkv[ROWS * NQKV];             // [b*T][3072]: q cols 0-1023, k 1024-2047, v 2048-3071
__device__ float g_vt [ZHD * HDn * Tn];          // V^T per (b,h), tf32-rounded
__device__ float g_att[ROWS * Dn];
__device__ float g_x2 [ROWS * Dn];
__device__ float g_h2 [ROWS * Dn];
__device__ float g_mid[ROWS * 4 * Dn];
__device__ float g_wqkvT[NQKV * Dn];             // [3072][1024]: fused B operand
__device__ float g_woT [Dn * Dn];
__device__ float g_w1T [4 * Dn * Dn];            // [4D][D]
__device__ float g_w2T [4 * Dn * Dn];            // [D][4D]

// ---------------------------------------------------------------------------
__device__ __forceinline__ float rna(float x) {
    unsigned u;
    asm("cvt.rna.tf32.f32 %0, %1;" : "=r"(u) : "f"(x));
    return __uint_as_float(u);
}
__device__ __forceinline__ unsigned smem_u32(const void* p) {
    return (unsigned)__cvta_generic_to_shared(p);
}
__device__ __forceinline__ void cp16(unsigned dst, const void* src) {
    asm volatile("cp.async.cg.shared.global [%0],[%1],16;\n" :: "r"(dst), "l"(src));
}
#define CP_COMMIT()  asm volatile("cp.async.commit_group;" ::: "memory")
#define CP_WAIT(n)   asm volatile("cp.async.wait_group %0;" :: "n"(n) : "memory")

#define MMA_TF32(d, a, b) \
    asm volatile("mma.sync.aligned.m16n8k8.row.col.f32.tf32.tf32.f32 " \
                 "{%0,%1,%2,%3},{%4,%5,%6,%7},{%8,%9},{%0,%1,%2,%3};\n" \
                 : "+f"((d)[0]), "+f"((d)[1]), "+f"((d)[2]), "+f"((d)[3]) \
                 : "r"((a)[0]), "r"((a)[1]), "r"((a)[2]), "r"((a)[3]), \
                   "r"((b)[0]), "r"((b)[1]))

// ---------------------------------------------------------------------------
// transpose + tf32-round: in tile [R][C] fp32 -> out [C][R]; per-z offsets
// via (z/dz)*sIn1 + (z%mz)*sIn2 on input, z*sOut on output.
// ---------------------------------------------------------------------------
__global__ void transpose_rna(const float* __restrict__ in,
                              float* __restrict__ outp,
                              int ldin, long long sIn1, int dz, long long sIn2, int mz,
                              int ldout, long long sOut)
{
    __shared__ float t[32][33];
    int z = blockIdx.z;
    in   += (long long)(z / dz) * sIn1 + (long long)(z % mz) * sIn2;
    outp += (long long)z * sOut;
    int c0 = blockIdx.x * 32, r0 = blockIdx.y * 32;
    int tx = threadIdx.x, ty = threadIdx.y;
#pragma unroll
    for (int i = 0; i < 32; i += 8)
        t[ty + i][tx] = in[(long long)(r0 + ty + i) * ldin + c0 + tx];
    __syncthreads();
#pragma unroll
    for (int i = 0; i < 32; i += 8)
        outp[(long long)(c0 + ty + i) * ldout + r0 + tx] = rna(t[tx][ty + i]);
}

// ---------------------------------------------------------------------------
// gemm_tf32: single-pass TF32 GEMM. C = A @ B^T (+epi).  (R8-proven structure)
//   A fp32 [M,K] (tf32-rounded by producer); B fp32 [N,K] (rounded); fp32 acc.
//   EPI: 0 -> rounded fp32 C; 1 -> bias+relu, rounded fp32 C;
//        2 -> bias+residual, exact fp32 C.
// BM=128, BN=128, BK=32, 256 thr (warps 2m x 4n, warp tile 64x32),
// 2-stage cp.async double buffer, XOR-swizzled smem (conflict-free).
// Dynamic smem: 2 * 8192 floats = 64 KB.
// ---------------------------------------------------------------------------
template <int EPI>
__launch_bounds__(256, 2)
__global__ void gemm_tf32(const float* __restrict__ A,
                          const float* __restrict__ B,
                          float* __restrict__ C,
                          const float* __restrict__ bias,
                          const float* __restrict__ res,
                          int N, int K, int lda, int ldb, int ldc,
                          long long sA1, int dA, long long sA2, int mA,
                          long long sB1, int dB, long long sB2, int mB,
                          long long sC1, int dC, long long sC2, int mC)
{
    extern __shared__ float sm[];      // stage s: A at s*8192, B at s*8192+4096

    const int m0 = blockIdx.y * 128;
    const int n0 = blockIdx.x * 128;

    const int z = blockIdx.z;
    A += (long long)(z / dA) * sA1 + (long long)(z % mA) * sA2;
    B += (long long)(z / dB) * sB1 + (long long)(z % mB) * sB2;
    const long long coff = (long long)(z / dC) * sC1 + (long long)(z % mC) * sC2;
    C += coff;
    if (EPI == 2) res += coff;

    const int tid  = threadIdx.x;
    const int lane = tid & 31;
    const int w    = tid >> 5;
    const int wm   = (w & 1) * 64;
    const int wn   = (w >> 1) * 32;
    const int q    = lane >> 2;
    const int kb   = lane & 3;
    const int nk   = K / 32;

    // loader constants: thread handles rows (tid>>3)+32i, float4 group tid&7
    const int lrow = tid >> 3;
    const int lg   = tid & 7;
    const unsigned lsw = ((unsigned)(lg * 4)) ^ ((unsigned)((lrow & 7) * 4));

    float acc[4][4][4];
#pragma unroll
    for (int mt = 0; mt < 4; mt++)
#pragma unroll
        for (int nt = 0; nt < 4; nt++)
#pragma unroll
            for (int j = 0; j < 4; j++) acc[mt][nt][j] = 0.f;

    auto load_stage = [&](int st, int kt) {
        float* sb = sm + st * 8192;
        const int k0 = kt * 32;
#pragma unroll
        for (int i = 0; i < 4; i++) {
            int row = lrow + 32 * i;
            unsigned off = row * 32 + lsw;
            cp16(smem_u32(sb + off),        A + (long long)(m0 + row) * lda + k0 + lg * 4);
            cp16(smem_u32(sb + 4096 + off), B + (long long)(n0 + row) * ldb + k0 + lg * 4);
        }
        CP_COMMIT();
    };

    load_stage(0, 0);

    for (int kt = 0; kt < nk; kt++) {
        if (kt + 1 < nk) {
            load_stage((kt + 1) & 1, kt + 1);
            CP_WAIT(1);
        } else {
            CP_WAIT(0);
        }
        __syncthreads();

        const unsigned* su = (const unsigned*)(sm + (kt & 1) * 8192);
        const unsigned qx = (unsigned)(q << 2);
#pragma unroll
        for (int s4 = 0; s4 < 4; s4++) {
            const int k8 = s4 * 8;
            const unsigned g0 = ((unsigned)k8 ^ qx) + kb;
            const unsigned g1 = ((unsigned)(k8 + 4) ^ qx) + kb;
            unsigned a[4][4], b[4][2];
#pragma unroll
            for (int mt = 0; mt < 4; mt++) {
                const int r = wm + mt * 16 + q;
                a[mt][0] = su[r * 32 + g0];
                a[mt][1] = su[(r + 8) * 32 + g0];
                a[mt][2] = su[r * 32 + g1];
                a[mt][3] = su[(r + 8) * 32 + g1];
            }
#pragma unroll
            for (int nt = 0; nt < 4; nt++) {
                const int rn = wn + nt * 8 + q;
                b[nt][0] = su[4096 + rn * 32 + g0];
                b[nt][1] = su[4096 + rn * 32 + g1];
            }
#pragma unroll
            for (int mt = 0; mt < 4; mt++)
#pragma unroll
                for (int nt = 0; nt < 4; nt++)
                    MMA_TF32(acc[mt][nt], a[mt], b[nt]);
        }
        __syncthreads();
    }

    // ---- epilogue
#pragma unroll
    for (int mt = 0; mt < 4; mt++)
#pragma unroll
        for (int nt = 0; nt < 4; nt++) {
            const float* a4 = acc[mt][nt];
            const long long r0 = m0 + wm + mt * 16 + q;
            const long long r1 = r0 + 8;
            const int cc = n0 + wn + nt * 8 + kb * 2;
            if (EPI == 0) {
                *reinterpret_cast<float2*>(&C[r0 * ldc + cc]) =
                    make_float2(rna(a4[0]), rna(a4[1]));
                *reinterpret_cast<float2*>(&C[r1 * ldc + cc]) =
                    make_float2(rna(a4[2]), rna(a4[3]));
            } else if (EPI == 1) {
                float2 bv = *reinterpret_cast<const float2*>(&bias[cc]);
                *reinterpret_cast<float2*>(&C[r0 * ldc + cc]) =
                    make_float2(rna(fmaxf(a4[0] + bv.x, 0.f)),
                                rna(fmaxf(a4[1] + bv.y, 0.f)));
                *reinterpret_cast<float2*>(&C[r1 * ldc + cc]) =
                    make_float2(rna(fmaxf(a4[2] + bv.x, 0.f)),
                                rna(fmaxf(a4[3] + bv.y, 0.f)));
            } else {
                float2 bv = *reinterpret_cast<const float2*>(&bias[cc]);
                float2 q0 = *reinterpret_cast<const float2*>(&res[r0 * ldc + cc]);
                float2 q1 = *reinterpret_cast<const float2*>(&res[r1 * ldc + cc]);
                *reinterpret_cast<float2*>(&C[r0 * ldc + cc]) =
                    make_float2(a4[0] + bv.x + q0.x, a4[1] + bv.y + q0.y);
                *reinterpret_cast<float2*>(&C[r1 * ldc + cc]) =
                    make_float2(a4[2] + bv.x + q1.x, a4[3] + bv.y + q1.y);
            }
        }
}

// ---------------------------------------------------------------------------
// Flash attention, single-pass TF32 (R8-proven serial-tile structure).
// Q/K read from fused qkv [4096][3072] (row stride 3072, head col offset).
// grid = (Tn/128, ZHD), block = 256. Static smem 8704 floats.
// ---------------------------------------------------------------------------
__launch_bounds__(256)
__global__ void flash_tf32(const float* __restrict__ qkv,
                           const float* __restrict__ vt,
                           float* __restrict__ att)
{
    __shared__ __align__(16) float s_u[8704];   // Q staging 128x68 / K(0..4095)+V(4096..8191)

    const int z  = blockIdx.y;
    const int m0 = blockIdx.x * 128;
    const int tid = threadIdx.x, lane = tid & 31, w = tid >> 5;
    const int q  = lane >> 2;
    const int kb = lane & 3;
    const unsigned qx = (unsigned)(q << 2);

    const long long bbase = (long long)(z >> 4) * Tn * NQKV;   // batch row base
    const int hcol = (z & 15) * HDn;                           // head column

    // ---- stage Q, extract tf32 A-fragments (scale 2^-5 folded; values pre-rounded)
    unsigned qf[8][4];
    {
        const float* Qg = qkv + bbase + (long long)m0 * NQKV + hcol;
#pragma unroll
        for (int i = 0; i < 8; i++) {
            int idx = tid + 256 * i;
            int r = idx >> 4, c4 = idx & 15;
            float4 v = *reinterpret_cast<const float4*>(Qg + (long long)r * NQKV + c4 * 4);
            *reinterpret_cast<float4*>(s_u + r * 68 + c4 * 4) = v;
        }
        __syncthreads();
        const int ra = w * 16 + q;
        const float sc = 0.03125f;      // exact power of 2, keeps tf32-exactness
#pragma unroll
        for (int c = 0; c < 8; c++) {
            qf[c][0] = __float_as_uint(s_u[ra * 68 + c * 8 + kb] * sc);
            qf[c][1] = __float_as_uint(s_u[(ra + 8) * 68 + c * 8 + kb] * sc);
            qf[c][2] = __float_as_uint(s_u[ra * 68 + c * 8 + kb + 4] * sc);
            qf[c][3] = __float_as_uint(s_u[(ra + 8) * 68 + c * 8 + kb + 4] * sc);
        }
        __syncthreads();
    }

    float m0s = -1e30f, m1s = -1e30f;
    float l0 = 0.f, l1 = 0.f;
    float acc_o[8][4];
#pragma unroll
    for (int nt = 0; nt < 8; nt++)
#pragma unroll
        for (int j = 0; j < 4; j++) acc_o[nt][j] = 0.f;

    const int nkb = blockIdx.x * 2 + 2;
    const float* Kg = qkv + bbase + 1024 + hcol;
    const float* Vg = vt + (long long)z * HDn * Tn;
    const int rga = m0 + w * 16 + q;
    const int rgb = rga + 8;

    // loader constants: rows (tid>>4)+16i, float4 group tid&15
    const int lrow = tid >> 4;
    const int lg   = tid & 15;
    const unsigned lsw = ((unsigned)(lg * 4)) ^ ((unsigned)((lrow & 7) * 4));

    for (int it = 0; it < nkb; it++) {
        // ---- load K (64x64) and V^T (64x64) tiles, swizzled
        {
#pragma unroll
            for (int i = 0; i < 4; i++) {
                int row = lrow + 16 * i;
                unsigned off = row * 64 + lsw;
                cp16(smem_u32(s_u + off),
                     Kg + (long long)(it * 64 + row) * NQKV + lg * 4);
                cp16(smem_u32(s_u + 4096 + off),
                     Vg + (long long)row * Tn + it * 64 + lg * 4);
            }
            CP_COMMIT();
            CP_WAIT(0);
        }
        __syncthreads();
        const unsigned* su = (const unsigned*)s_u;

        // ---- S = Q K^T (tf32)
        float s[8][4];
#pragma unroll
        for (int nt = 0; nt < 8; nt++)
#pragma unroll
            for (int j = 0; j < 4; j++) s[nt][j] = 0.f;

#pragma unroll
        for (int c = 0; c < 8; c++) {
            const int c8 = c * 8;
            const unsigned g0 = ((unsigned)c8 ^ qx) + kb;
            const unsigned g1 = ((unsigned)(c8 + 4) ^ qx) + kb;
#pragma unroll
            for (int nt = 0; nt < 8; nt++) {
                const int ro = (nt * 8 + q) * 64;
                unsigned bb[2] = { su[ro + g0], su[ro + g1] };
                MMA_TF32(s[nt], qf[c], bb);
            }
        }

        // ---- causal mask
        const int cb = kb * 2;
        if (it * 64 + 63 > rga) {
#pragma unroll
            for (int nt = 0; nt < 8; nt++) {
                int cg = it * 64 + nt * 8 + cb;
                if (cg > rga)     s[nt][0] = -1e30f;
                if (cg + 1 > rga) s[nt][1] = -1e30f;
                if (cg > rgb)     s[nt][2] = -1e30f;
                if (cg + 1 > rgb) s[nt][3] = -1e30f;
            }
        }

        // ---- online softmax
        float ml0 = -1e30f, ml1 = -1e30f;
#pragma unroll
        for (int nt = 0; nt < 8; nt++) {
            ml0 = fmaxf(ml0, fmaxf(s[nt][0], s[nt][1]));
            ml1 = fmaxf(ml1, fmaxf(s[nt][2], s[nt][3]));
        }
        ml0 = fmaxf(ml0, __shfl_xor_sync(0xffffffffu, ml0, 1));
        ml0 = fmaxf(ml0, __shfl_xor_sync(0xffffffffu, ml0, 2));
        ml1 = fmaxf(ml1, __shfl_xor_sync(0xffffffffu, ml1, 1));
        ml1 = fmaxf(ml1, __shfl_xor_sync(0xffffffffu, ml1, 2));
        float mn0 = fmaxf(m0s, ml0), mn1 = fmaxf(m1s, ml1);
        float al0 = __expf(m0s - mn0), al1 = __expf(m1s - mn1);
        m0s = mn0; m1s = mn1;

        float rs0 = 0.f, rs1 = 0.f;
#pragma unroll
        for (int nt = 0; nt < 8; nt++) {
            s[nt][0] = __expf(s[nt][0] - mn0);
            s[nt][1] = __expf(s[nt][1] - mn0);
            s[nt][2] = __expf(s[nt][2] - mn1);
            s[nt][3] = __expf(s[nt][3] - mn1);
            rs0 += s[nt][0] + s[nt][1];
            rs1 += s[nt][2] + s[nt][3];
        }
        rs0 += __shfl_xor_sync(0xffffffffu, rs0, 1);
        rs0 += __shfl_xor_sync(0xffffffffu, rs0, 2);
        rs1 += __shfl_xor_sync(0xffffffffu, rs1, 1);
        rs1 += __shfl_xor_sync(0xffffffffu, rs1, 2);
        l0 = l0 * al0 + rs0;
        l1 = l1 * al1 + rs1;
#pragma unroll
        for (int nt = 0; nt < 8; nt++) {
            acc_o[nt][0] *= al0; acc_o[nt][1] *= al0;
            acc_o[nt][2] *= al1; acc_o[nt][3] *= al1;
        }

        // ---- O += P V: shuffle-transpose P C-frag -> A-frag per key chunk
        const int src0 = (lane & ~3) | (kb >> 1);
        const int src1 = src0 + 2;
        const bool od = (kb & 1);
#pragma unroll
        for (int kc = 0; kc < 8; kc++) {
            float x0 = __shfl_sync(0xffffffffu, s[kc][0], src0);
            float x1 = __shfl_sync(0xffffffffu, s[kc][1], src0);
            float x2 = __shfl_sync(0xffffffffu, s[kc][2], src0);
            float x3 = __shfl_sync(0xffffffffu, s[kc][3], src0);
            float y0 = __shfl_sync(0xffffffffu, s[kc][0], src1);
            float y1 = __shfl_sync(0xffffffffu, s[kc][1], src1);
            float y2 = __shfl_sync(0xffffffffu, s[kc][2], src1);
            float y3 = __shfl_sync(0xffffffffu, s[kc][3], src1);
            unsigned pa[4];
            pa[0] = __float_as_uint(rna(od ? x1 : x0));
            pa[1] = __float_as_uint(rna(od ? x3 : x2));
            pa[2] = __float_as_uint(rna(od ? y1 : y0));
            pa[3] = __float_as_uint(rna(od ? y3 : y2));
            const int k8 = kc * 8;
            const unsigned g0 = ((unsigned)k8 ^ qx) + kb;
            const unsigned g1 = ((unsigned)(k8 + 4) ^ qx) + kb;
#pragma unroll
            for (int nt = 0; nt < 8; nt++) {
                const int ro = 4096 + (nt * 8 + q) * 64;
                unsigned bb[2] = { su[ro + g0], su[ro + g1] };
                MMA_TF32(acc_o[nt], pa, bb);
            }
        }
        __syncthreads();     // protect smem before next tile's cp.async
    }

    // ---- epilogue: normalize, round, write concat layout [b][t][h*64+e]
    const float i0 = 1.f / l0, i1 = 1.f / l1;
    float* op = att + (long long)(z >> 4) * Tn * Dn + (z & 15) * HDn;
    const int cb = kb * 2;
#pragma unroll
    for (int nt = 0; nt < 8; nt++) {
        *reinterpret_cast<float2*>(op + (long long)rga * Dn + nt * 8 + cb) =
            make_float2(rna(acc_o[nt][0] * i0), rna(acc_o[nt][1] * i0));
        *reinterpret_cast<float2*>(op + (long long)rgb * Dn + nt * 8 + cb) =
            make_float2(rna(acc_o[nt][2] * i1), rna(acc_o[nt][3] * i1));
    }
}

// ---------------------------------------------------------------------------
// LayerNorm over last dim (1024), output tf32-rounded fp32.
// ---------------------------------------------------------------------------
__launch_bounds__(256)
__global__ void ln_kernel(const float* __restrict__ x,
                          const float* __restrict__ g,
                          const float* __restrict__ be,
                          float* __restrict__ outp)
{
    long long row = blockIdx.x;
    const float* xr = x + row * Dn;
    int tid = threadIdx.x;

    float v[4];
    float s = 0.f;
#pragma unroll
    for (int i = 0; i < 4; i++) { v[i] = xr[tid + 256 * i]; s += v[i]; }

    __shared__ float red[8];
    __shared__ float sh_mu, sh_rstd;

#pragma unroll
    for (int o = 16; o > 0; o >>= 1) s += __shfl_xor_sync(0xffffffffu, s, o);
    if ((tid & 31) == 0) red[tid >> 5] = s;
    __syncthreads();
    if (tid == 0) {
        float t = 0.f;
        for (int i = 0; i < 8; i++) t += red[i];
        sh_mu = t * (1.0f / Dn);
    }
    __syncthreads();
    float mu = sh_mu;

    float ss = 0.f;
#pragma unroll
    for (int i = 0; i < 4; i++) { float d = v[i] - mu; ss += d * d; }
#pragma unroll
    for (int o = 16; o > 0; o >>= 1) ss += __shfl_xor_sync(0xffffffffu, ss, o);
    if ((tid & 31) == 0) red[tid >> 5] = ss;
    __syncthreads();
    if (tid == 0) {
        float t = 0.f;
        for (int i = 0; i < 8; i++) t += red[i];
        sh_rstd = rsqrtf(t * (1.0f / Dn) + 1e-5f);
    }
    __syncthreads();
    float rstd = sh_rstd;

#pragma unroll
    for (int i = 0; i < 4; i++) {
        int c = tid + 256 * i;
        outp[row * Dn + c] = rna((v[i] - mu) * rstd * g[c] + be[c]);
    }
}

// ---------------------------------------------------------------------------
extern "C" void kernel_launch(void* const* d_in, const int* in_sizes, int n_in,
                              void* d_out, int out_size)
{
    const float* x   = (const float*)d_in[0];
    const float* Wq  = (const float*)d_in[1];
    const float* Wk  = (const float*)d_in[2];
    const float* Wv  = (const float*)d_in[3];
    const float* Wo  = (const float*)d_in[4];
    const float* bo  = (const float*)d_in[5];
    const float* W1  = (const float*)d_in[6];
    const float* b1  = (const float*)d_in[7];
    const float* W2  = (const float*)d_in[8];
    const float* b2  = (const float*)d_in[9];
    const float* g1  = (const float*)d_in[10];
    const float* be1 = (const float*)d_in[11];
    const float* g2  = (const float*)d_in[12];
    const float* be2 = (const float*)d_in[13];
    float* out = (float*)d_out;

    float *h1, *qkv, *vt, *att, *x2, *h2, *mid;
    float *wqkvT, *woT, *w1T, *w2T;
    cudaGetSymbolAddress((void**)&h1,   g_h1);
    cudaGetSymbolAddress((void**)&qkv,  g_qkv);
    cudaGetSymbolAddress((void**)&vt,   g_vt);
    cudaGetSymbolAddress((void**)&att,  g_att);
    cudaGetSymbolAddress((void**)&x2,   g_x2);
    cudaGetSymbolAddress((void**)&h2,   g_h2);
    cudaGetSymbolAddress((void**)&mid,  g_mid);
    cudaGetSymbolAddress((void**)&wqkvT, g_wqkvT);
    cudaGetSymbolAddress((void**)&woT,  g_woT);
    cudaGetSymbolAddress((void**)&w1T,  g_w1T);
    cudaGetSymbolAddress((void**)&w2T,  g_w2T);

    const int GSMEM = 2 * 8192 * 4;    // 64 KB (2-stage, R8-proven)
    cudaFuncSetAttribute(gemm_tf32<0>, cudaFuncAttributeMaxDynamicSharedMemorySize, GSMEM);
    cudaFuncSetAttribute(gemm_tf32<1>, cudaFuncAttributeMaxDynamicSharedMemorySize, GSMEM);
    cudaFuncSetAttribute(gemm_tf32<2>, cudaFuncAttributeMaxDynamicSharedMemorySize, GSMEM);

    dim3 blk(256);
    dim3 tblk(32, 8);

    // ---- weight transposes (+ tf32 rounding) into fused [3072][1024] B operand:
    // rows 0-1023: Wq (head h -> rows h*64..), 1024-2047: Wk, 2048-3071: Wv.
    transpose_rna<<<dim3(HDn / 32, Dn / 32, Hn), tblk>>>(
        Wq, wqkvT + 0 * Dn * Dn, HDn, (long long)Dn * HDn, 1, 0LL, 1,
        Dn, (long long)HDn * Dn);
    transpose_rna<<<dim3(HDn / 32, Dn / 32, Hn), tblk>>>(
        Wk, wqkvT + 1 * Dn * Dn, HDn, (long long)Dn * HDn, 1, 0LL, 1,
        Dn, (long long)HDn * Dn);
    transpose_rna<<<dim3(HDn / 32, Dn / 32, Hn), tblk>>>(
        Wv, wqkvT + 2 * Dn * Dn, HDn, (long long)Dn * HDn, 1, 0LL, 1,
        Dn, (long long)HDn * Dn);
    transpose_rna<<<dim3(Dn / 32, Dn / 32, 1), tblk>>>(
        Wo, woT, Dn, 0LL, 1, 0LL, 1, Dn, 0LL);
    transpose_rna<<<dim3(4 * Dn / 32, Dn / 32, 1), tblk>>>(
        W1, w1T, 4 * Dn, 0LL, 1, 0LL, 1, Dn, 0LL);
    transpose_rna<<<dim3(Dn / 32, 4 * Dn / 32, 1), tblk>>>(
        W2, w2T, Dn, 0LL, 1, 0LL, 1, 4 * Dn, 0LL);

    // ---- LN1: x -> h1 (rounded)
    ln_kernel<<<ROWS, blk>>>(x, g1, be1, h1);

    // ---- fused QKV as ONE exact-size GEMM: qkv[4096][3072] = h1 @ wqkvT^T
    gemm_tf32<0><<<dim3(NQKV / 128, ROWS / 128, 1), blk, GSMEM>>>(
        h1, wqkvT, qkv, nullptr, nullptr,
        NQKV, Dn, Dn, Dn, NQKV,
        0LL, 1, 0LL, 1, 0LL, 1, 0LL, 1, 0LL, 1, 0LL, 1);

    // ---- V transpose (rounded): qkv cols [2048 + h*64 .. +63] -> vt [z][HD][T]
    // input per z=(b,h): offset (z/16)*T*3072 + (z%16)*64 + 2048
    transpose_rna<<<dim3(HDn / 32, Tn / 32, ZHD), tblk>>>(
        qkv + 2048, vt, NQKV,
        (long long)Tn * NQKV, Hn, (long long)HDn, Hn,
        Tn, (long long)HDn * Tn);

    // ---- flash attention (tf32) -> att (rounded, concat layout)
    flash_tf32<<<dim3(Tn / 128, ZHD), blk>>>(qkv, vt, att);

    // ---- O projection + bias + residual: x2 = x + att @ Wo + bo
    gemm_tf32<2><<<dim3(Dn / 128, ROWS / 128, 1), blk, GSMEM>>>(
        att, woT, x2, bo, x,
        Dn, Dn, Dn, Dn, Dn,
        0LL, 1, 0LL, 1, 0LL, 1, 0LL, 1, 0LL, 1, 0LL, 1);

    // ---- LN2: x2 -> h2 (rounded)
    ln_kernel<<<ROWS, blk>>>(x2, g2, be2, h2);

    // ---- FFN1: mid = relu(h2 @ W1 + b1) (rounded)
    gemm_tf32<1><<<dim3(4 * Dn / 128, ROWS / 128, 1), blk, GSMEM>>>(
        h2, w1T, mid, b1, nullptr,
        4 * Dn, Dn, Dn, Dn, 4 * Dn,
        0LL, 1, 0LL, 1, 0LL, 1, 0LL, 1, 0LL, 1, 0LL, 1);

    // ---- FFN2: out = x2 + mid @ W2 + b2
    gemm_tf32<2><<<dim3(Dn / 128, ROWS / 128, 1), blk, GSMEM>>>(
        mid, w2T, out, b2, x2,
        Dn, 4 * Dn, 4 * Dn, 4 * Dn, Dn,
        0LL, 1, 0LL, 1, 0LL, 1, 0LL, 1, 0LL, 1, 0LL, 1);
}

// round 12
// speedup vs baseline: 1.9386x; 1.7819x over previous
#include <cuda_runtime.h>
#include <cuda_fp16.h>

// Problem constants
#define Tn   2048
#define Dn   1024
#define Hn   16
#define HDn  64
#define Bn   2
#define ROWS (Bn * Tn)   // 4096
#define ZHD  (Bn * Hn)   // 32
#define NQKV 3072        // q|k|v fused output width

// ---------------- scratch (static device globals; no allocations) ----------
__device__ __half g_h1 [ROWS * Dn];
__device__ __half g_qkv[ROWS * NQKV];            // [b*T][3072]: q|k|v (q pre-scaled via Wq)
__device__ __half g_vt [ZHD * HDn * Tn];         // V^T per (b,h)
__device__ __half g_att[ROWS * Dn];
__device__ float  g_x2 [ROWS * Dn];
__device__ __half g_h2 [ROWS * Dn];
__device__ __half g_mid[ROWS * 4 * Dn];
__device__ __half g_wqkvT[NQKV * Dn];            // [3072][1024] fused B operand
__device__ __half g_woT [Dn * Dn];
__device__ __half g_w1T [4 * Dn * Dn];           // [4D][D]
__device__ __half g_w2T [4 * Dn * Dn];           // [D][4D]

// ---------------------------------------------------------------------------
__device__ __forceinline__ unsigned smem_u32(const void* p) {
    return (unsigned)__cvta_generic_to_shared(p);
}
__device__ __forceinline__ void cp16(unsigned dst, const void* src) {
    asm volatile("cp.async.cg.shared.global [%0],[%1],16;\n" :: "r"(dst), "l"(src));
}
#define CP_COMMIT()  asm volatile("cp.async.commit_group;" ::: "memory")
#define CP_WAIT(n)   asm volatile("cp.async.wait_group %0;" :: "n"(n) : "memory")

#define MMA_FP16(d, a, b) \
    asm volatile("mma.sync.aligned.m16n8k16.row.col.f32.f16.f16.f32 " \
                 "{%0,%1,%2,%3},{%4,%5,%6,%7},{%8,%9},{%0,%1,%2,%3};\n" \
                 : "+f"((d)[0]), "+f"((d)[1]), "+f"((d)[2]), "+f"((d)[3]) \
                 : "r"((a)[0]), "r"((a)[1]), "r"((a)[2]), "r"((a)[3]), \
                   "r"((b)[0]), "r"((b)[1]))

__device__ __forceinline__ unsigned pack_h2(float a, float b) {
    __half2 h = __floats2half2_rn(a, b);
    return *reinterpret_cast<unsigned*>(&h);
}

// ---------------------------------------------------------------------------
// transpose fp32 -> fp16 (with scale): in tile [R][C] -> out [C][R], per-z z*sIn.
// ---------------------------------------------------------------------------
__global__ void transpose_f2h(const float* __restrict__ in,
                              __half* __restrict__ outp,
                              int ldin, long long sIn, int ldout, long long sOut,
                              float scale)
{
    __shared__ float t[32][33];
    int z = blockIdx.z;
    in   += (long long)z * sIn;
    outp += (long long)z * sOut;
    int c0 = blockIdx.x * 32, r0 = blockIdx.y * 32;
    int tx = threadIdx.x, ty = threadIdx.y;
#pragma unroll
    for (int i = 0; i < 32; i += 8)
        t[ty + i][tx] = in[(long long)(r0 + ty + i) * ldin + c0 + tx];
    __syncthreads();
#pragma unroll
    for (int i = 0; i < 32; i += 8)
        outp[(long long)(c0 + ty + i) * ldout + r0 + tx] =
            __float2half_rn(t[tx][ty + i] * scale);
}

// transpose fp16 -> fp16: in tile [R][C] -> out [C][R]; z offsets (z/dz)*sIn1+(z%mz)*sIn2.
__global__ void transpose_h(const __half* __restrict__ in,
                            __half* __restrict__ outp,
                            int ldin, long long sIn1, int dz, long long sIn2, int mz,
                            int ldout, long long sOut)
{
    __shared__ __half t[32][34];
    int z = blockIdx.z;
    in   += (long long)(z / dz) * sIn1 + (long long)(z % mz) * sIn2;
    outp += (long long)z * sOut;
    int c0 = blockIdx.x * 32, r0 = blockIdx.y * 32;
    int tx = threadIdx.x, ty = threadIdx.y;
#pragma unroll
    for (int i = 0; i < 32; i += 8)
        t[ty + i][tx] = in[(long long)(r0 + ty + i) * ldin + c0 + tx];
    __syncthreads();
#pragma unroll
    for (int i = 0; i < 32; i += 8)
        outp[(long long)(c0 + ty + i) * ldout + r0 + tx] = t[tx][ty + i];
}

// ---------------------------------------------------------------------------
// gemm_fp16: single-pass FP16 GEMM (fp32 accum). C = A @ B^T (+epi).
//   A fp16 [M,K]; B fp16 [N,K].
//   EPI: 0 -> fp16 C; 1 -> bias+relu -> fp16 C; 2 -> bias+residual -> fp32 C.
// BM=128, BN=128, BK=64, 256 thr (warps 2m x 4n, warp tile 64x32),
// 2-stage cp.async double buffer, XOR-swizzled smem.
// smem row = 64 halfs = 32 words; stage = (128+128)*32 words = 8192 words = 32KB;
// 2 stages = 64 KB dynamic.
// ---------------------------------------------------------------------------
template <int EPI>
__launch_bounds__(256, 2)
__global__ void gemm_fp16(const __half* __restrict__ A,
                          const __half* __restrict__ B,
                          float* __restrict__ C,
                          __half* __restrict__ Ch,
                          const float* __restrict__ bias,
                          const float* __restrict__ res,
                          int N, int K, int lda, int ldb, int ldc)
{
    extern __shared__ unsigned sm[];   // stage s: A at s*8192, B at s*8192+4096

    const int m0 = blockIdx.y * 128;
    const int n0 = blockIdx.x * 128;

    const int tid  = threadIdx.x;
    const int lane = tid & 31;
    const int w    = tid >> 5;
    const int wm   = (w & 1) * 64;
    const int wn   = (w >> 1) * 32;
    const int q    = lane >> 2;
    const int kb   = lane & 3;
    const int nk   = K / 64;

    // loader: thread handles rows (tid>>3)+32i, 16B chunk tid&7 (8 chunks/row)
    const int lrow = tid >> 3;
    const int lg   = tid & 7;
    const unsigned lsw = ((unsigned)(lg * 4)) ^ ((unsigned)((lrow & 7) * 4));

    float acc[4][4][4];
#pragma unroll
    for (int mt = 0; mt < 4; mt++)
#pragma unroll
        for (int nt = 0; nt < 4; nt++)
#pragma unroll
            for (int j = 0; j < 4; j++) acc[mt][nt][j] = 0.f;

    auto load_stage = [&](int st, int kt) {
        unsigned* sb = sm + st * 8192;
        const int k0 = kt * 64;
#pragma unroll
        for (int i = 0; i < 4; i++) {
            int row = lrow + 32 * i;
            unsigned off = row * 32 + lsw;
            cp16(smem_u32(sb + off),        A + (long long)(m0 + row) * lda + k0 + lg * 8);
            cp16(smem_u32(sb + 4096 + off), B + (long long)(n0 + row) * ldb + k0 + lg * 8);
        }
        CP_COMMIT();
    };

    load_stage(0, 0);

    for (int kt = 0; kt < nk; kt++) {
        if (kt + 1 < nk) {
            load_stage((kt + 1) & 1, kt + 1);
            CP_WAIT(1);
        } else {
            CP_WAIT(0);
        }
        __syncthreads();

        const unsigned* su = sm + (kt & 1) * 8192;
        const unsigned qx = (unsigned)(q << 2);
#pragma unroll
        for (int c = 0; c < 4; c++) {              // 4 x k16 chunks
            const unsigned g0 = ((unsigned)(c * 8) ^ qx) + kb;
            const unsigned g1 = ((unsigned)(c * 8 + 4) ^ qx) + kb;
            unsigned a[4][4], b[4][2];
#pragma unroll
            for (int mt = 0; mt < 4; mt++) {
                const int r = wm + mt * 16 + q;
                a[mt][0] = su[r * 32 + g0];
                a[mt][1] = su[(r + 8) * 32 + g0];
                a[mt][2] = su[r * 32 + g1];
                a[mt][3] = su[(r + 8) * 32 + g1];
            }
#pragma unroll
            for (int nt = 0; nt < 4; nt++) {
                const int rn = wn + nt * 8 + q;
                b[nt][0] = su[4096 + rn * 32 + g0];
                b[nt][1] = su[4096 + rn * 32 + g1];
            }
#pragma unroll
            for (int mt = 0; mt < 4; mt++)
#pragma unroll
                for (int nt = 0; nt < 4; nt++)
                    MMA_FP16(acc[mt][nt], a[mt], b[nt]);
        }
        __syncthreads();
    }

    // ---- epilogue
#pragma unroll
    for (int mt = 0; mt < 4; mt++)
#pragma unroll
        for (int nt = 0; nt < 4; nt++) {
            const float* a4 = acc[mt][nt];
            const long long r0 = m0 + wm + mt * 16 + q;
            const long long r1 = r0 + 8;
            const int cc = n0 + wn + nt * 8 + kb * 2;
            if (EPI == 0) {
                *reinterpret_cast<unsigned*>(&Ch[r0 * ldc + cc]) = pack_h2(a4[0], a4[1]);
                *reinterpret_cast<unsigned*>(&Ch[r1 * ldc + cc]) = pack_h2(a4[2], a4[3]);
            } else if (EPI == 1) {
                float2 bv = *reinterpret_cast<const float2*>(&bias[cc]);
                *reinterpret_cast<unsigned*>(&Ch[r0 * ldc + cc]) =
                    pack_h2(fmaxf(a4[0] + bv.x, 0.f), fmaxf(a4[1] + bv.y, 0.f));
                *reinterpret_cast<unsigned*>(&Ch[r1 * ldc + cc]) =
                    pack_h2(fmaxf(a4[2] + bv.x, 0.f), fmaxf(a4[3] + bv.y, 0.f));
            } else {
                float2 bv = *reinterpret_cast<const float2*>(&bias[cc]);
                float2 q0 = *reinterpret_cast<const float2*>(&res[r0 * ldc + cc]);
                float2 q1 = *reinterpret_cast<const float2*>(&res[r1 * ldc + cc]);
                *reinterpret_cast<float2*>(&C[r0 * ldc + cc]) =
                    make_float2(a4[0] + bv.x + q0.x, a4[1] + bv.y + q0.y);
                *reinterpret_cast<float2*>(&C[r1 * ldc + cc]) =
                    make_float2(a4[2] + bv.x + q1.x, a4[3] + bv.y + q1.y);
            }
        }
}

// ---------------------------------------------------------------------------
// Flash attention, FP16 operands / fp32 softmax+accum (R8-proven serial tiles).
// Q pre-scaled by 2^-5 (folded into Wq). Q/K from fused qkv; V^T from vt.
// grid = (Tn/128, ZHD), block = 256. Static smem: 8192 words = 32 KB
// (Q 0..4095, K 4096..6143, V 6144..8191).
// ---------------------------------------------------------------------------
__launch_bounds__(256)
__global__ void flash_fp16(const __half* __restrict__ qkv,
                           const __half* __restrict__ vt,
                           __half* __restrict__ att)
{
    __shared__ __align__(16) unsigned s_w[8192];

    const int z  = blockIdx.y;
    const int m0 = blockIdx.x * 128;
    const int tid = threadIdx.x, lane = tid & 31, w = tid >> 5;
    const int q  = lane >> 2;
    const int kb = lane & 3;
    const unsigned qx = (unsigned)(q << 2);

    const long long bbase = (long long)(z >> 4) * Tn * NQKV;   // batch row base
    const int hcol = (z & 15) * HDn;                           // head column

    // ---- stage Q (128x64 halfs, swizzled), extract fp16 A-fragments
    unsigned qf[4][4];
    {
        const __half* Qg = qkv + bbase + (long long)m0 * NQKV + hcol;
#pragma unroll
        for (int i = 0; i < 4; i++) {
            int idx = tid + 256 * i;           // 0..1023 chunks
            int r = idx >> 3, ch = idx & 7;
            unsigned sw = r * 32 + (((unsigned)(ch * 4)) ^ ((unsigned)((r & 7) * 4)));
            cp16(smem_u32(s_w + sw), Qg + (long long)r * NQKV + ch * 8);
        }
        CP_COMMIT();
        CP_WAIT(0);
        __syncthreads();
        const int ra = w * 16 + q;
#pragma unroll
        for (int c = 0; c < 4; c++) {
            const unsigned g0 = ((unsigned)(c * 8) ^ qx) + kb;
            const unsigned g1 = ((unsigned)(c * 8 + 4) ^ qx) + kb;
            qf[c][0] = s_w[ra * 32 + g0];
            qf[c][1] = s_w[(ra + 8) * 32 + g0];
            qf[c][2] = s_w[ra * 32 + g1];
            qf[c][3] = s_w[(ra + 8) * 32 + g1];
        }
        __syncthreads();
    }

    float m0s = -1e30f, m1s = -1e30f;
    float l0 = 0.f, l1 = 0.f;
    float acc_o[8][4];
#pragma unroll
    for (int nt = 0; nt < 8; nt++)
#pragma unroll
        for (int j = 0; j < 4; j++) acc_o[nt][j] = 0.f;

    const int nkb = blockIdx.x * 2 + 2;
    const __half* Kg = qkv + bbase + 1024 + hcol;
    const __half* Vg = vt + (long long)z * HDn * Tn;
    const int rga = m0 + w * 16 + q;
    const int rgb = rga + 8;

    for (int it = 0; it < nkb; it++) {
        // ---- load K (64x64) and V^T (64x64) fp16 tiles, swizzled
        {
#pragma unroll
            for (int i = 0; i < 2; i++) {
                int idx = tid + 256 * i;       // 0..511 chunks
                int r = idx >> 3, ch = idx & 7;
                unsigned sw = r * 32 + (((unsigned)(ch * 4)) ^ ((unsigned)((r & 7) * 4)));
                cp16(smem_u32(s_w + 4096 + sw),
                     Kg + (long long)(it * 64 + r) * NQKV + ch * 8);
                cp16(smem_u32(s_w + 6144 + sw),
                     Vg + (long long)r * Tn + it * 64 + ch * 8);
            }
            CP_COMMIT();
            CP_WAIT(0);
        }
        __syncthreads();

        // ---- S = Q K^T (fp16, fp32 accum)
        float s[8][4];
#pragma unroll
        for (int nt = 0; nt < 8; nt++)
#pragma unroll
            for (int j = 0; j < 4; j++) s[nt][j] = 0.f;

#pragma unroll
        for (int c = 0; c < 4; c++) {
            const unsigned g0 = ((unsigned)(c * 8) ^ qx) + kb;
            const unsigned g1 = ((unsigned)(c * 8 + 4) ^ qx) + kb;
#pragma unroll
            for (int nt = 0; nt < 8; nt++) {
                const int ro = 4096 + (nt * 8 + q) * 32;
                unsigned bb[2] = { s_w[ro + g0], s_w[ro + g1] };
                MMA_FP16(s[nt], qf[c], bb);
            }
        }

        // ---- causal mask
        const int cb = kb * 2;
        if (it * 64 + 63 > rga) {
#pragma unroll
            for (int nt = 0; nt < 8; nt++) {
                int cg = it * 64 + nt * 8 + cb;
                if (cg > rga)     s[nt][0] = -1e30f;
                if (cg + 1 > rga) s[nt][1] = -1e30f;
                if (cg > rgb)     s[nt][2] = -1e30f;
                if (cg + 1 > rgb) s[nt][3] = -1e30f;
            }
        }

        // ---- online softmax (fp32)
        float ml0 = -1e30f, ml1 = -1e30f;
#pragma unroll
        for (int nt = 0; nt < 8; nt++) {
            ml0 = fmaxf(ml0, fmaxf(s[nt][0], s[nt][1]));
            ml1 = fmaxf(ml1, fmaxf(s[nt][2], s[nt][3]));
        }
        ml0 = fmaxf(ml0, __shfl_xor_sync(0xffffffffu, ml0, 1));
        ml0 = fmaxf(ml0, __shfl_xor_sync(0xffffffffu, ml0, 2));
        ml1 = fmaxf(ml1, __shfl_xor_sync(0xffffffffu, ml1, 1));
        ml1 = fmaxf(ml1, __shfl_xor_sync(0xffffffffu, ml1, 2));
        float mn0 = fmaxf(m0s, ml0), mn1 = fmaxf(m1s, ml1);
        float al0 = __expf(m0s - mn0), al1 = __expf(m1s - mn1);
        m0s = mn0; m1s = mn1;

        float rs0 = 0.f, rs1 = 0.f;
#pragma unroll
        for (int nt = 0; nt < 8; nt++) {
            s[nt][0] = __expf(s[nt][0] - mn0);
            s[nt][1] = __expf(s[nt][1] - mn0);
            s[nt][2] = __expf(s[nt][2] - mn1);
            s[nt][3] = __expf(s[nt][3] - mn1);
            rs0 += s[nt][0] + s[nt][1];
            rs1 += s[nt][2] + s[nt][3];
        }
        rs0 += __shfl_xor_sync(0xffffffffu, rs0, 1);
        rs0 += __shfl_xor_sync(0xffffffffu, rs0, 2);
        rs1 += __shfl_xor_sync(0xffffffffu, rs1, 1);
        rs1 += __shfl_xor_sync(0xffffffffu, rs1, 2);
        l0 = l0 * al0 + rs0;
        l1 = l1 * al1 + rs1;
#pragma unroll
        for (int nt = 0; nt < 8; nt++) {
            acc_o[nt][0] *= al0; acc_o[nt][1] *= al0;
            acc_o[nt][2] *= al1; acc_o[nt][3] *= al1;
        }

        // ---- P C-frag -> fp16 A-frags (k16 identity: no shuffles) and PV
#pragma unroll
        for (int c = 0; c < 4; c++) {
            unsigned pa[4];
            pa[0] = pack_h2(s[2 * c][0],     s[2 * c][1]);
            pa[1] = pack_h2(s[2 * c][2],     s[2 * c][3]);
            pa[2] = pack_h2(s[2 * c + 1][0], s[2 * c + 1][1]);
            pa[3] = pack_h2(s[2 * c + 1][2], s[2 * c + 1][3]);
            const unsigned g0 = ((unsigned)(c * 8) ^ qx) + kb;
            const unsigned g1 = ((unsigned)(c * 8 + 4) ^ qx) + kb;
#pragma unroll
            for (int nt = 0; nt < 8; nt++) {
                const int ro = 6144 + (nt * 8 + q) * 32;
                unsigned bb[2] = { s_w[ro + g0], s_w[ro + g1] };
                MMA_FP16(acc_o[nt], pa, bb);
            }
        }
        __syncthreads();     // protect smem before next tile's cp.async
    }

    // ---- epilogue: normalize, write fp16 concat layout [b][t][h*64+e]
    const float i0 = 1.f / l0, i1 = 1.f / l1;
    __half* op = att + (long long)(z >> 4) * Tn * Dn + (z & 15) * HDn;
    const int cb = kb * 2;
#pragma unroll
    for (int nt = 0; nt < 8; nt++) {
        *reinterpret_cast<unsigned*>(op + (long long)rga * Dn + nt * 8 + cb) =
            pack_h2(acc_o[nt][0] * i0, acc_o[nt][1] * i0);
        *reinterpret_cast<unsigned*>(op + (long long)rgb * Dn + nt * 8 + cb) =
            pack_h2(acc_o[nt][2] * i1, acc_o[nt][3] * i1);
    }
}

// ---------------------------------------------------------------------------
// LayerNorm over last dim (1024), output fp16.
// ---------------------------------------------------------------------------
__launch_bounds__(256)
__global__ void ln_kernel(const float* __restrict__ x,
                          const float* __restrict__ g,
                          const float* __restrict__ be,
                          __half* __restrict__ outp)
{
    long long row = blockIdx.x;
    const float* xr = x + row * Dn;
    int tid = threadIdx.x;

    float v[4];
    float s = 0.f;
#pragma unroll
    for (int i = 0; i < 4; i++) { v[i] = xr[tid + 256 * i]; s += v[i]; }

    __shared__ float red[8];
    __shared__ float sh_mu, sh_rstd;

#pragma unroll
    for (int o = 16; o > 0; o >>= 1) s += __shfl_xor_sync(0xffffffffu, s, o);
    if ((tid & 31) == 0) red[tid >> 5] = s;
    __syncthreads();
    if (tid == 0) {
        float t = 0.f;
        for (int i = 0; i < 8; i++) t += red[i];
        sh_mu = t * (1.0f / Dn);
    }
    __syncthreads();
    float mu = sh_mu;

    float ss = 0.f;
#pragma unroll
    for (int i = 0; i < 4; i++) { float d = v[i] - mu; ss += d * d; }
#pragma unroll
    for (int o = 16; o > 0; o >>= 1) ss += __shfl_xor_sync(0xffffffffu, ss, o);
    if ((tid & 31) == 0) red[tid >> 5] = ss;
    __syncthreads();
    if (tid == 0) {
        float t = 0.f;
        for (int i = 0; i < 8; i++) t += red[i];
        sh_rstd = rsqrtf(t * (1.0f / Dn) + 1e-5f);
    }
    __syncthreads();
    float rstd = sh_rstd;

#pragma unroll
    for (int i = 0; i < 4; i++) {
        int c = tid + 256 * i;
        outp[row * Dn + c] = __float2half_rn((v[i] - mu) * rstd * g[c] + be[c]);
    }
}

// ---------------------------------------------------------------------------
extern "C" void kernel_launch(void* const* d_in, const int* in_sizes, int n_in,
                              void* d_out, int out_size)
{
    const float* x   = (const float*)d_in[0];
    const float* Wq  = (const float*)d_in[1];
    const float* Wk  = (const float*)d_in[2];
    const float* Wv  = (const float*)d_in[3];
    const float* Wo  = (const float*)d_in[4];
    const float* bo  = (const float*)d_in[5];
    const float* W1  = (const float*)d_in[6];
    const float* b1  = (const float*)d_in[7];
    const float* W2  = (const float*)d_in[8];
    const float* b2  = (const float*)d_in[9];
    const float* g1  = (const float*)d_in[10];
    const float* be1 = (const float*)d_in[11];
    const float* g2  = (const float*)d_in[12];
    const float* be2 = (const float*)d_in[13];
    float* out = (float*)d_out;

    float *x2;
    __half *h1, *qkv, *vt, *att, *h2, *mid;
    __half *wqkvT, *woT, *w1T, *w2T;
    cudaGetSymbolAddress((void**)&h1,   g_h1);
    cudaGetSymbolAddress((void**)&qkv,  g_qkv);
    cudaGetSymbolAddress((void**)&vt,   g_vt);
    cudaGetSymbolAddress((void**)&att,  g_att);
    cudaGetSymbolAddress((void**)&x2,   g_x2);
    cudaGetSymbolAddress((void**)&h2,   g_h2);
    cudaGetSymbolAddress((void**)&mid,  g_mid);
    cudaGetSymbolAddress((void**)&wqkvT, g_wqkvT);
    cudaGetSymbolAddress((void**)&woT,  g_woT);
    cudaGetSymbolAddress((void**)&w1T,  g_w1T);
    cudaGetSymbolAddress((void**)&w2T,  g_w2T);

    const int GSMEM = 2 * 8192 * 4;    // 64 KB
    cudaFuncSetAttribute(gemm_fp16<0>, cudaFuncAttributeMaxDynamicSharedMemorySize, GSMEM);
    cudaFuncSetAttribute(gemm_fp16<1>, cudaFuncAttributeMaxDynamicSharedMemorySize, GSMEM);
    cudaFuncSetAttribute(gemm_fp16<2>, cudaFuncAttributeMaxDynamicSharedMemorySize, GSMEM);

    dim3 blk(256);
    dim3 tblk(32, 8);

    // ---- weight transposes (fp32 -> fp16) into fused [3072][1024] B operand.
    // Wq scaled by 2^-5 (exact exponent shift) = folds the attention scale into q.
    transpose_f2h<<<dim3(HDn / 32, Dn / 32, Hn), tblk>>>(
        Wq, wqkvT + 0 * Dn * Dn, HDn, (long long)Dn * HDn, Dn, (long long)HDn * Dn,
        0.03125f);
    transpose_f2h<<<dim3(HDn / 32, Dn / 32, Hn), tblk>>>(
        Wk, wqkvT + 1 * Dn * Dn, HDn, (long long)Dn * HDn, Dn, (long long)HDn * Dn,
        1.0f);
    transpose_f2h<<<dim3(HDn / 32, Dn / 32, Hn), tblk>>>(
        Wv, wqkvT + 2 * Dn * Dn, HDn, (long long)Dn * HDn, Dn, (long long)HDn * Dn,
        1.0f);
    transpose_f2h<<<dim3(Dn / 32, Dn / 32, 1), tblk>>>(
        Wo, woT, Dn, 0LL, Dn, 0LL, 1.0f);
    transpose_f2h<<<dim3(4 * Dn / 32, Dn / 32, 1), tblk>>>(
        W1, w1T, 4 * Dn, 0LL, Dn, 0LL, 1.0f);
    transpose_f2h<<<dim3(Dn / 32, 4 * Dn / 32, 1), tblk>>>(
        W2, w2T, Dn, 0LL, 4 * Dn, 0LL, 1.0f);

    // ---- LN1: x -> h1 (fp16)
    ln_kernel<<<ROWS, blk>>>(x, g1, be1, h1);

    // ---- fused QKV as ONE exact-size GEMM: qkv[4096][3072] = h1 @ wqkvT^T (fp16 out)
    gemm_fp16<0><<<dim3(NQKV / 128, ROWS / 128, 1), blk, GSMEM>>>(
        h1, wqkvT, nullptr, qkv, nullptr, nullptr,
        NQKV, Dn, Dn, Dn, NQKV);

    // ---- V transpose (fp16): qkv cols [2048 + h*64 ..] -> vt [z][HD][T]
    transpose_h<<<dim3(HDn / 32, Tn / 32, ZHD), tblk>>>(
        qkv + 2048, vt, NQKV,
        (long long)Tn * NQKV, Hn, (long long)HDn, Hn,
        Tn, (long long)HDn * Tn);

    // ---- flash attention (fp16) -> att (fp16, concat layout)
    flash_fp16<<<dim3(Tn / 128, ZHD), blk>>>(qkv, vt, att);

    // ---- O projection + bias + residual: x2 = x + att @ Wo + bo (fp32 out)
    gemm_fp16<2><<<dim3(Dn / 128, ROWS / 128, 1), blk, GSMEM>>>(
        att, woT, x2, nullptr, bo, x,
        Dn, Dn, Dn, Dn, Dn);

    // ---- LN2: x2 -> h2 (fp16)
    ln_kernel<<<ROWS, blk>>>(x2, g2, be2, h2);

    // ---- FFN1: mid = relu(h2 @ W1 + b1) (fp16 out)
    gemm_fp16<1><<<dim3(4 * Dn / 128, ROWS / 128, 1), blk, GSMEM>>>(
        h2, w1T, nullptr, mid, b1, nullptr,
        4 * Dn, Dn, Dn, Dn, 4 * Dn);

    // ---- FFN2: out = x2 + mid @ W2 + b2 (fp32 out)
    gemm_fp16<2><<<dim3(Dn / 128, ROWS / 128, 1), blk, GSMEM>>>(
        mid, w2T, out, nullptr, b2, x2,
        Dn, 4 * Dn, 4 * Dn, 4 * Dn, Dn);
}

// round 13
// speedup vs baseline: 2.1039x; 1.0853x over previous
#include <cuda_runtime.h>
#include <cuda_fp16.h>

// Problem constants
#define Tn   2048
#define Dn   1024
#define Hn   16
#define HDn  64
#define Bn   2
#define ROWS (Bn * Tn)   // 4096
#define ZHD  (Bn * Hn)   // 32
#define NQKV 3072        // q|k|v fused output width

// ---------------- scratch (static device globals; no allocations) ----------
__device__ __half g_h1 [ROWS * Dn];
__device__ __half g_qkv[ROWS * NQKV];            // [b*T][3072]: q|k|v (q pre-scaled via Wq)
__device__ __half g_vt [ZHD * HDn * Tn];         // V^T per (b,h)
__device__ __half g_att[ROWS * Dn];
__device__ float  g_x2 [ROWS * Dn];
__device__ __half g_h2 [ROWS * Dn];
__device__ __half g_mid[ROWS * 4 * Dn];
__device__ __half g_wqkvT[NQKV * Dn];            // [3072][1024] fused B operand
__device__ __half g_woT [Dn * Dn];
__device__ __half g_w1T [4 * Dn * Dn];           // [4D][D]
__device__ __half g_w2T [4 * Dn * Dn];           // [D][4D]

// ---------------------------------------------------------------------------
__device__ __forceinline__ unsigned smem_u32(const void* p) {
    return (unsigned)__cvta_generic_to_shared(p);
}
__device__ __forceinline__ void cp16(unsigned dst, const void* src) {
    asm volatile("cp.async.cg.shared.global [%0],[%1],16;\n" :: "r"(dst), "l"(src));
}
#define CP_COMMIT()  asm volatile("cp.async.commit_group;" ::: "memory")
#define CP_WAIT(n)   asm volatile("cp.async.wait_group %0;" :: "n"(n) : "memory")

#define MMA_FP16(d, a, b) \
    asm volatile("mma.sync.aligned.m16n8k16.row.col.f32.f16.f16.f32 " \
                 "{%0,%1,%2,%3},{%4,%5,%6,%7},{%8,%9},{%0,%1,%2,%3};\n" \
                 : "+f"((d)[0]), "+f"((d)[1]), "+f"((d)[2]), "+f"((d)[3]) \
                 : "r"((a)[0]), "r"((a)[1]), "r"((a)[2]), "r"((a)[3]), \
                   "r"((b)[0]), "r"((b)[1]))

// Warp-collective fragment load: 4 x m8n8 b16 matrices.
// Lane group lg = lane>>3 supplies the 8 row addresses of matrix lg.
#define LDSM_X4(r0, r1, r2, r3, addr) \
    asm volatile("ldmatrix.sync.aligned.m8n8.x4.shared.b16 {%0,%1,%2,%3},[%4];\n" \
                 : "=r"(r0), "=r"(r1), "=r"(r2), "=r"(r3) : "r"(addr))

__device__ __forceinline__ unsigned pack_h2(float a, float b) {
    __half2 h = __floats2half2_rn(a, b);
    return *reinterpret_cast<unsigned*>(&h);
}

// ---------------------------------------------------------------------------
// transpose fp32 -> fp16 (with scale): in tile [R][C] -> out [C][R], per-z z*sIn.
// ---------------------------------------------------------------------------
__global__ void transpose_f2h(const float* __restrict__ in,
                              __half* __restrict__ outp,
                              int ldin, long long sIn, int ldout, long long sOut,
                              float scale)
{
    __shared__ float t[32][33];
    int z = blockIdx.z;
    in   += (long long)z * sIn;
    outp += (long long)z * sOut;
    int c0 = blockIdx.x * 32, r0 = blockIdx.y * 32;
    int tx = threadIdx.x, ty = threadIdx.y;
#pragma unroll
    for (int i = 0; i < 32; i += 8)
        t[ty + i][tx] = in[(long long)(r0 + ty + i) * ldin + c0 + tx];
    __syncthreads();
#pragma unroll
    for (int i = 0; i < 32; i += 8)
        outp[(long long)(c0 + ty + i) * ldout + r0 + tx] =
            __float2half_rn(t[tx][ty + i] * scale);
}

// transpose fp16 -> fp16: in tile [R][C] -> out [C][R]; z offsets (z/dz)*sIn1+(z%mz)*sIn2.
__global__ void transpose_h(const __half* __restrict__ in,
                            __half* __restrict__ outp,
                            int ldin, long long sIn1, int dz, long long sIn2, int mz,
                            int ldout, long long sOut)
{
    __shared__ __half t[32][34];
    int z = blockIdx.z;
    in   += (long long)(z / dz) * sIn1 + (long long)(z % mz) * sIn2;
    outp += (long long)z * sOut;
    int c0 = blockIdx.x * 32, r0 = blockIdx.y * 32;
    int tx = threadIdx.x, ty = threadIdx.y;
#pragma unroll
    for (int i = 0; i < 32; i += 8)
        t[ty + i][tx] = in[(long long)(r0 + ty + i) * ldin + c0 + tx];
    __syncthreads();
#pragma unroll
    for (int i = 0; i < 32; i += 8)
        outp[(long long)(c0 + ty + i) * ldout + r0 + tx] = t[tx][ty + i];
}

// ---------------------------------------------------------------------------
// gemm_fp16: single-pass FP16 GEMM (fp32 accum), ldmatrix fragment loads.
//   C = A @ B^T (+epi). A fp16 [M,K]; B fp16 [N,K].
//   EPI: 0 -> fp16 C; 1 -> bias+relu -> fp16 C; 2 -> bias+residual -> fp32 C.
// BM=128, BN=128, BK=64, 256 thr (warps 2m x 4n, warp tile 64x32),
// 2-stage cp.async double buffer, XOR-swizzled smem (LDSM-compatible).
// ---------------------------------------------------------------------------
template <int EPI>
__launch_bounds__(256, 2)
__global__ void gemm_fp16(const __half* __restrict__ A,
                          const __half* __restrict__ B,
                          float* __restrict__ C,
                          __half* __restrict__ Ch,
                          const float* __restrict__ bias,
                          const float* __restrict__ res,
                          int N, int K, int lda, int ldb, int ldc)
{
    extern __shared__ unsigned sm[];   // stage s: A at s*8192 words, B at +4096 words

    const int m0 = blockIdx.y * 128;
    const int n0 = blockIdx.x * 128;

    const int tid  = threadIdx.x;
    const int lane = tid & 31;
    const int w    = tid >> 5;
    const int wm   = (w & 1) * 64;
    const int wn   = (w >> 1) * 32;
    const int q    = lane >> 2;
    const int kb   = lane & 3;
    const int nk   = K / 64;

    // ldmatrix lane mapping
    const int mi = lane >> 3;          // matrix index group 0..3
    const int ri = lane & 7;           // row within matrix
    const unsigned aRow = wm + (mi & 1) * 8 + ri;   // + mt*16
    const unsigned bRow = wn + (mi >> 1) * 8 + ri;  // + p*16
    const int caA = mi >> 1;           // chunk half for A (k lo/hi)
    const int caB = mi & 1;            // chunk half for B

    // loader: thread handles rows (tid>>3)+32i, 16B chunk tid&7
    const int lrow = tid >> 3;
    const int lg   = tid & 7;
    const unsigned lsw = ((unsigned)(lg * 4)) ^ ((unsigned)((lrow & 7) * 4));

    float acc[4][4][4];
#pragma unroll
    for (int mt = 0; mt < 4; mt++)
#pragma unroll
        for (int nt = 0; nt < 4; nt++)
#pragma unroll
            for (int j = 0; j < 4; j++) acc[mt][nt][j] = 0.f;

    auto load_stage = [&](int st, int kt) {
        unsigned* sb = sm + st * 8192;
        const int k0 = kt * 64;
#pragma unroll
        for (int i = 0; i < 4; i++) {
            int row = lrow + 32 * i;
            unsigned off = row * 32 + lsw;
            cp16(smem_u32(sb + off),        A + (long long)(m0 + row) * lda + k0 + lg * 8);
            cp16(smem_u32(sb + 4096 + off), B + (long long)(n0 + row) * ldb + k0 + lg * 8);
        }
        CP_COMMIT();
    };

    load_stage(0, 0);

    const unsigned sbase0 = smem_u32(sm);

    for (int kt = 0; kt < nk; kt++) {
        if (kt + 1 < nk) {
            load_stage((kt + 1) & 1, kt + 1);
            CP_WAIT(1);
        } else {
            CP_WAIT(0);
        }
        __syncthreads();

        const unsigned sA = sbase0 + (kt & 1) * 32768;         // stage A byte base
        const unsigned sB = sA + 16384;                        // stage B byte base
#pragma unroll
        for (int c = 0; c < 4; c++) {              // 4 x k16 chunks
            unsigned a[4][4], b[4][2];
            const unsigned swzA = (unsigned)(((2 * c + caA) ^ ri) << 4);
            const unsigned swzB = (unsigned)(((2 * c + caB) ^ ri) << 4);
#pragma unroll
            for (int mt = 0; mt < 4; mt++) {
                unsigned addr = sA + (aRow + mt * 16) * 128 + swzA;
                LDSM_X4(a[mt][0], a[mt][1], a[mt][2], a[mt][3], addr);
            }
#pragma unroll
            for (int p = 0; p < 2; p++) {
                unsigned addr = sB + (bRow + p * 16) * 128 + swzB;
                LDSM_X4(b[2 * p][0], b[2 * p][1], b[2 * p + 1][0], b[2 * p + 1][1], addr);
            }
#pragma unroll
            for (int mt = 0; mt < 4; mt++)
#pragma unroll
                for (int nt = 0; nt < 4; nt++)
                    MMA_FP16(acc[mt][nt], a[mt], b[nt]);
        }
        __syncthreads();
    }

    // ---- epilogue
#pragma unroll
    for (int mt = 0; mt < 4; mt++)
#pragma unroll
        for (int nt = 0; nt < 4; nt++) {
            const float* a4 = acc[mt][nt];
            const long long r0 = m0 + wm + mt * 16 + q;
            const long long r1 = r0 + 8;
            const int cc = n0 + wn + nt * 8 + kb * 2;
            if (EPI == 0) {
                *reinterpret_cast<unsigned*>(&Ch[r0 * ldc + cc]) = pack_h2(a4[0], a4[1]);
                *reinterpret_cast<unsigned*>(&Ch[r1 * ldc + cc]) = pack_h2(a4[2], a4[3]);
            } else if (EPI == 1) {
                float2 bv = *reinterpret_cast<const float2*>(&bias[cc]);
                *reinterpret_cast<unsigned*>(&Ch[r0 * ldc + cc]) =
                    pack_h2(fmaxf(a4[0] + bv.x, 0.f), fmaxf(a4[1] + bv.y, 0.f));
                *reinterpret_cast<unsigned*>(&Ch[r1 * ldc + cc]) =
                    pack_h2(fmaxf(a4[2] + bv.x, 0.f), fmaxf(a4[3] + bv.y, 0.f));
            } else {
                float2 bv = *reinterpret_cast<const float2*>(&bias[cc]);
                float2 q0 = *reinterpret_cast<const float2*>(&res[r0 * ldc + cc]);
                float2 q1 = *reinterpret_cast<const float2*>(&res[r1 * ldc + cc]);
                *reinterpret_cast<float2*>(&C[r0 * ldc + cc]) =
                    make_float2(a4[0] + bv.x + q0.x, a4[1] + bv.y + q0.y);
                *reinterpret_cast<float2*>(&C[r1 * ldc + cc]) =
                    make_float2(a4[2] + bv.x + q1.x, a4[3] + bv.y + q1.y);
            }
        }
}

// ---------------------------------------------------------------------------
// Flash attention, FP16 operands / fp32 softmax+accum; ldmatrix K/V loads.
// Q pre-scaled by 2^-5 (folded into Wq). grid = (Tn/128, ZHD), block = 256.
// Static smem: 8192 words = 32 KB (Q 0..4095, K 4096..6143, V 6144..8191).
// ---------------------------------------------------------------------------
__launch_bounds__(256)
__global__ void flash_fp16(const __half* __restrict__ qkv,
                           const __half* __restrict__ vt,
                           __half* __restrict__ att)
{
    __shared__ __align__(16) unsigned s_w[8192];

    const int z  = blockIdx.y;
    const int m0 = blockIdx.x * 128;
    const int tid = threadIdx.x, lane = tid & 31, w = tid >> 5;
    const int q  = lane >> 2;
    const int kb = lane & 3;
    const unsigned qx = (unsigned)(q << 2);

    // ldmatrix lane mapping (B-style: tile pair p, chunk half caB)
    const int mi = lane >> 3;
    const int ri = lane & 7;
    const unsigned bRow = (unsigned)((mi >> 1) * 8 + ri);   // + p*16
    const int caB = mi & 1;

    const long long bbase = (long long)(z >> 4) * Tn * NQKV;   // batch row base
    const int hcol = (z & 15) * HDn;                           // head column

    // ---- stage Q (128x64 halfs, swizzled), extract fp16 A-fragments (scalar, once)
    unsigned qf[4][4];
    {
        const __half* Qg = qkv + bbase + (long long)m0 * NQKV + hcol;
#pragma unroll
        for (int i = 0; i < 4; i++) {
            int idx = tid + 256 * i;           // 0..1023 chunks
            int r = idx >> 3, ch = idx & 7;
            unsigned sw = r * 32 + (((unsigned)(ch * 4)) ^ ((unsigned)((r & 7) * 4)));
            cp16(smem_u32(s_w + sw), Qg + (long long)r * NQKV + ch * 8);
        }
        CP_COMMIT();
        CP_WAIT(0);
        __syncthreads();
        const int ra = w * 16 + q;
#pragma unroll
        for (int c = 0; c < 4; c++) {
            const unsigned g0 = ((unsigned)(c * 8) ^ qx) + kb;
            const unsigned g1 = ((unsigned)(c * 8 + 4) ^ qx) + kb;
            qf[c][0] = s_w[ra * 32 + g0];
            qf[c][1] = s_w[(ra + 8) * 32 + g0];
            qf[c][2] = s_w[ra * 32 + g1];
            qf[c][3] = s_w[(ra + 8) * 32 + g1];
        }
        __syncthreads();
    }

    float m0s = -1e30f, m1s = -1e30f;
    float l0 = 0.f, l1 = 0.f;
    float acc_o[8][4];
#pragma unroll
    for (int nt = 0; nt < 8; nt++)
#pragma unroll
        for (int j = 0; j < 4; j++) acc_o[nt][j] = 0.f;

    const int nkb = blockIdx.x * 2 + 2;
    const __half* Kg = qkv + bbase + 1024 + hcol;
    const __half* Vg = vt + (long long)z * HDn * Tn;
    const int rga = m0 + w * 16 + q;
    const int rgb = rga + 8;

    const unsigned kBase = smem_u32(s_w) + 16384;   // K tile byte base (word 4096)
    const unsigned vBase = smem_u32(s_w) + 24576;   // V tile byte base (word 6144)

    for (int it = 0; it < nkb; it++) {
        // ---- load K (64x64) and V^T (64x64) fp16 tiles, swizzled
        {
#pragma unroll
            for (int i = 0; i < 2; i++) {
                int idx = tid + 256 * i;       // 0..511 chunks
                int r = idx >> 3, ch = idx & 7;
                unsigned sw = r * 32 + (((unsigned)(ch * 4)) ^ ((unsigned)((r & 7) * 4)));
                cp16(smem_u32(s_w + 4096 + sw),
                     Kg + (long long)(it * 64 + r) * NQKV + ch * 8);
                cp16(smem_u32(s_w + 6144 + sw),
                     Vg + (long long)r * Tn + it * 64 + ch * 8);
            }
            CP_COMMIT();
            CP_WAIT(0);
        }
        __syncthreads();

        // ---- S = Q K^T (fp16, fp32 accum); K frags via ldmatrix
        float s[8][4];
#pragma unroll
        for (int nt = 0; nt < 8; nt++)
#pragma unroll
            for (int j = 0; j < 4; j++) s[nt][j] = 0.f;

#pragma unroll
        for (int c = 0; c < 4; c++) {
            unsigned bbf[8][2];
            const unsigned swzB = (unsigned)(((2 * c + caB) ^ ri) << 4);
#pragma unroll
            for (int p = 0; p < 4; p++) {
                unsigned addr = kBase + (bRow + p * 16) * 128 + swzB;
                LDSM_X4(bbf[2 * p][0], bbf[2 * p][1],
                        bbf[2 * p + 1][0], bbf[2 * p + 1][1], addr);
            }
#pragma unroll
            for (int nt = 0; nt < 8; nt++)
                MMA_FP16(s[nt], qf[c], bbf[nt]);
        }

        // ---- causal mask
        const int cb = kb * 2;
        if (it * 64 + 63 > rga) {
#pragma unroll
            for (int nt = 0; nt < 8; nt++) {
                int cg = it * 64 + nt * 8 + cb;
                if (cg > rga)     s[nt][0] = -1e30f;
                if (cg + 1 > rga) s[nt][1] = -1e30f;
                if (cg > rgb)     s[nt][2] = -1e30f;
                if (cg + 1 > rgb) s[nt][3] = -1e30f;
            }
        }

        // ---- online softmax (fp32)
        float ml0 = -1e30f, ml1 = -1e30f;
#pragma unroll
        for (int nt = 0; nt < 8; nt++) {
            ml0 = fmaxf(ml0, fmaxf(s[nt][0], s[nt][1]));
            ml1 = fmaxf(ml1, fmaxf(s[nt][2], s[nt][3]));
        }
        ml0 = fmaxf(ml0, __shfl_xor_sync(0xffffffffu, ml0, 1));
        ml0 = fmaxf(ml0, __shfl_xor_sync(0xffffffffu, ml0, 2));
        ml1 = fmaxf(ml1, __shfl_xor_sync(0xffffffffu, ml1, 1));
        ml1 = fmaxf(ml1, __shfl_xor_sync(0xffffffffu, ml1, 2));
        float mn0 = fmaxf(m0s, ml0), mn1 = fmaxf(m1s, ml1);
        float al0 = __expf(m0s - mn0), al1 = __expf(m1s - mn1);
        m0s = mn0; m1s = mn1;

        float rs0 = 0.f, rs1 = 0.f;
#pragma unroll
        for (int nt = 0; nt < 8; nt++) {
            s[nt][0] = __expf(s[nt][0] - mn0);
            s[nt][1] = __expf(s[nt][1] - mn0);
            s[nt][2] = __expf(s[nt][2] - mn1);
            s[nt][3] = __expf(s[nt][3] - mn1);
            rs0 += s[nt][0] + s[nt][1];
            rs1 += s[nt][2] + s[nt][3];
        }
        rs0 += __shfl_xor_sync(0xffffffffu, rs0, 1);
        rs0 += __shfl_xor_sync(0xffffffffu, rs0, 2);
        rs1 += __shfl_xor_sync(0xffffffffu, rs1, 1);
        rs1 += __shfl_xor_sync(0xffffffffu, rs1, 2);
        l0 = l0 * al0 + rs0;
        l1 = l1 * al1 + rs1;
#pragma unroll
        for (int nt = 0; nt < 8; nt++) {
            acc_o[nt][0] *= al0; acc_o[nt][1] *= al0;
            acc_o[nt][2] *= al1; acc_o[nt][3] *= al1;
        }

        // ---- P C-frag -> fp16 A-frags (k16 identity) and PV; V frags via ldmatrix
#pragma unroll
        for (int c = 0; c < 4; c++) {
            unsigned pa[4];
            pa[0] = pack_h2(s[2 * c][0],     s[2 * c][1]);
            pa[1] = pack_h2(s[2 * c][2],     s[2 * c][3]);
            pa[2] = pack_h2(s[2 * c + 1][0], s[2 * c + 1][1]);
            pa[3] = pack_h2(s[2 * c + 1][2], s[2 * c + 1][3]);
            unsigned bbf[8][2];
            const unsigned swzB = (unsigned)(((2 * c + caB) ^ ri) << 4);
#pragma unroll
            for (int p = 0; p < 4; p++) {
                unsigned addr = vBase + (bRow + p * 16) * 128 + swzB;
                LDSM_X4(bbf[2 * p][0], bbf[2 * p][1],
                        bbf[2 * p + 1][0], bbf[2 * p + 1][1], addr);
            }
#pragma unroll
            for (int nt = 0; nt < 8; nt++)
                MMA_FP16(acc_o[nt], pa, bbf[nt]);
        }
        __syncthreads();     // protect smem before next tile's cp.async
    }

    // ---- epilogue: normalize, write fp16 concat layout [b][t][h*64+e]
    const float i0 = 1.f / l0, i1 = 1.f / l1;
    __half* op = att + (long long)(z >> 4) * Tn * Dn + (z & 15) * HDn;
    const int cb = kb * 2;
#pragma unroll
    for (int nt = 0; nt < 8; nt++) {
        *reinterpret_cast<unsigned*>(op + (long long)rga * Dn + nt * 8 + cb) =
            pack_h2(acc_o[nt][0] * i0, acc_o[nt][1] * i0);
        *reinterpret_cast<unsigned*>(op + (long long)rgb * Dn + nt * 8 + cb) =
            pack_h2(acc_o[nt][2] * i1, acc_o[nt][3] * i1);
    }
}

// ---------------------------------------------------------------------------
// LayerNorm over last dim (1024), output fp16.
// ---------------------------------------------------------------------------
__launch_bounds__(256)
__global__ void ln_kernel(const float* __restrict__ x,
                          const float* __restrict__ g,
                          const float* __restrict__ be,
                          __half* __restrict__ outp)
{
    long long row = blockIdx.x;
    const float* xr = x + row * Dn;
    int tid = threadIdx.x;

    float v[4];
    float s = 0.f;
#pragma unroll
    for (int i = 0; i < 4; i++) { v[i] = xr[tid + 256 * i]; s += v[i]; }

    __shared__ float red[8];
    __shared__ float sh_mu, sh_rstd;

#pragma unroll
    for (int o = 16; o > 0; o >>= 1) s += __shfl_xor_sync(0xffffffffu, s, o);
    if ((tid & 31) == 0) red[tid >> 5] = s;
    __syncthreads();
    if (tid == 0) {
        float t = 0.f;
        for (int i = 0; i < 8; i++) t += red[i];
        sh_mu = t * (1.0f / Dn);
    }
    __syncthreads();
    float mu = sh_mu;

    float ss = 0.f;
#pragma unroll
    for (int i = 0; i < 4; i++) { float d = v[i] - mu; ss += d * d; }
#pragma unroll
    for (int o = 16; o > 0; o >>= 1) ss += __shfl_xor_sync(0xffffffffu, ss, o);
    if ((tid & 31) == 0) red[tid >> 5] = ss;
    __syncthreads();
    if (tid == 0) {
        float t = 0.f;
        for (int i = 0; i < 8; i++) t += red[i];
        sh_rstd = rsqrtf(t * (1.0f / Dn) + 1e-5f);
    }
    __syncthreads();
    float rstd = sh_rstd;

#pragma unroll
    for (int i = 0; i < 4; i++) {
        int c = tid + 256 * i;
        outp[row * Dn + c] = __float2half_rn((v[i] - mu) * rstd * g[c] + be[c]);
    }
}

// ---------------------------------------------------------------------------
extern "C" void kernel_launch(void* const* d_in, const int* in_sizes, int n_in,
                              void* d_out, int out_size)
{
    const float* x   = (const float*)d_in[0];
    const float* Wq  = (const float*)d_in[1];
    const float* Wk  = (const float*)d_in[2];
    const float* Wv  = (const float*)d_in[3];
    const float* Wo  = (const float*)d_in[4];
    const float* bo  = (const float*)d_in[5];
    const float* W1  = (const float*)d_in[6];
    const float* b1  = (const float*)d_in[7];
    const float* W2  = (const float*)d_in[8];
    const float* b2  = (const float*)d_in[9];
    const float* g1  = (const float*)d_in[10];
    const float* be1 = (const float*)d_in[11];
    const float* g2  = (const float*)d_in[12];
    const float* be2 = (const float*)d_in[13];
    float* out = (float*)d_out;

    float *x2;
    __half *h1, *qkv, *vt, *att, *h2, *mid;
    __half *wqkvT, *woT, *w1T, *w2T;
    cudaGetSymbolAddress((void**)&h1,   g_h1);
    cudaGetSymbolAddress((void**)&qkv,  g_qkv);
    cudaGetSymbolAddress((void**)&vt,   g_vt);
    cudaGetSymbolAddress((void**)&att,  g_att);
    cudaGetSymbolAddress((void**)&x2,   g_x2);
    cudaGetSymbolAddress((void**)&h2,   g_h2);
    cudaGetSymbolAddress((void**)&mid,  g_mid);
    cudaGetSymbolAddress((void**)&wqkvT, g_wqkvT);
    cudaGetSymbolAddress((void**)&woT,  g_woT);
    cudaGetSymbolAddress((void**)&w1T,  g_w1T);
    cudaGetSymbolAddress((void**)&w2T,  g_w2T);

    const int GSMEM = 2 * 8192 * 4;    // 64 KB
    cudaFuncSetAttribute(gemm_fp16<0>, cudaFuncAttributeMaxDynamicSharedMemorySize, GSMEM);
    cudaFuncSetAttribute(gemm_fp16<1>, cudaFuncAttributeMaxDynamicSharedMemorySize, GSMEM);
    cudaFuncSetAttribute(gemm_fp16<2>, cudaFuncAttributeMaxDynamicSharedMemorySize, GSMEM);

    dim3 blk(256);
    dim3 tblk(32, 8);

    // ---- weight transposes (fp32 -> fp16) into fused [3072][1024] B operand.
    // Wq scaled by 2^-5 (exact exponent shift) = folds the attention scale into q.
    transpose_f2h<<<dim3(HDn / 32, Dn / 32, Hn), tblk>>>(
        Wq, wqkvT + 0 * Dn * Dn, HDn, (long long)Dn * HDn, Dn, (long long)HDn * Dn,
        0.03125f);
    transpose_f2h<<<dim3(HDn / 32, Dn / 32, Hn), tblk>>>(
        Wk, wqkvT + 1 * Dn * Dn, HDn, (long long)Dn * HDn, Dn, (long long)HDn * Dn,
        1.0f);
    transpose_f2h<<<dim3(HDn / 32, Dn / 32, Hn), tblk>>>(
        Wv, wqkvT + 2 * Dn * Dn, HDn, (long long)Dn * HDn, Dn, (long long)HDn * Dn,
        1.0f);
    transpose_f2h<<<dim3(Dn / 32, Dn / 32, 1), tblk>>>(
        Wo, woT, Dn, 0LL, Dn, 0LL, 1.0f);
    transpose_f2h<<<dim3(4 * Dn / 32, Dn / 32, 1), tblk>>>(
        W1, w1T, 4 * Dn, 0LL, Dn, 0LL, 1.0f);
    transpose_f2h<<<dim3(Dn / 32, 4 * Dn / 32, 1), tblk>>>(
        W2, w2T, Dn, 0LL, 4 * Dn, 0LL, 1.0f);

    // ---- LN1: x -> h1 (fp16)
    ln_kernel<<<ROWS, blk>>>(x, g1, be1, h1);

    // ---- fused QKV as ONE exact-size GEMM: qkv[4096][3072] = h1 @ wqkvT^T (fp16 out)
    gemm_fp16<0><<<dim3(NQKV / 128, ROWS / 128, 1), blk, GSMEM>>>(
        h1, wqkvT, nullptr, qkv, nullptr, nullptr,
        NQKV, Dn, Dn, Dn, NQKV);

    // ---- V transpose (fp16): qkv cols [2048 + h*64 ..] -> vt [z][HD][T]
    transpose_h<<<dim3(HDn / 32, Tn / 32, ZHD), tblk>>>(
        qkv + 2048, vt, NQKV,
        (long long)Tn * NQKV, Hn, (long long)HDn, Hn,
        Tn, (long long)HDn * Tn);

    // ---- flash attention (fp16) -> att (fp16, concat layout)
    flash_fp16<<<dim3(Tn / 128, ZHD), blk>>>(qkv, vt, att);

    // ---- O projection + bias + residual: x2 = x + att @ Wo + bo (fp32 out)
    gemm_fp16<2><<<dim3(Dn / 128, ROWS / 128, 1), blk, GSMEM>>>(
        att, woT, x2, nullptr, bo, x,
        Dn, Dn, Dn, Dn, Dn);

    // ---- LN2: x2 -> h2 (fp16)
    ln_kernel<<<ROWS, blk>>>(x2, g2, be2, h2);

    // ---- FFN1: mid = relu(h2 @ W1 + b1) (fp16 out)
    gemm_fp16<1><<<dim3(4 * Dn / 128, ROWS / 128, 1), blk, GSMEM>>>(
        h2, w1T, nullptr, mid, b1, nullptr,
        4 * Dn, Dn, Dn, Dn, 4 * Dn);

    // ---- FFN2: out = x2 + mid @ W2 + b2 (fp32 out)
    gemm_fp16<2><<<dim3(Dn / 128, ROWS / 128, 1), blk, GSMEM>>>(
        mid, w2T, out, nullptr, b2, x2,
        Dn, 4 * Dn, 4 * Dn, 4 * Dn, Dn);
}